// round 12
// baseline (speedup 1.0000x reference)
#include <cuda_runtime.h>
#include <cuda_bf16.h>
#include <math.h>
#include <cstdint>

// ---------------- problem constants ----------------
#define BB 2
#define LL 2048
#define DIM 2048
#define HK 16
#define HV 32
#define DK 128
#define DV 128
#define KCONV 4
#define KEY_DIM (HK*DK)            // 2048
#define VAL_DIM (HV*DV)            // 4096
#define CONV_DIM (2*KEY_DIM+VAL_DIM) // 8192
#define MTOT (BB*LL)               // 4096

// ---------------- scratch ----------------
__device__ float g_qkv [ (size_t)BB*LL*CONV_DIM ];
__device__ float g_conv[ (size_t)BB*LL*CONV_DIM ];
__device__ float g_z   [ (size_t)BB*LL*VAL_DIM  ];
__device__ float g_eg  [ (size_t)BB*LL*HV ];
__device__ float g_beta[ (size_t)BB*LL*HV ];
__device__ float g_o   [ (size_t)BB*LL*VAL_DIM  ];
__device__ __nv_bfloat16 g_xp   [ (size_t)MTOT*DIM*2 ];
__device__ __nv_bfloat16 g_wqkvp[ (size_t)CONV_DIM*DIM*2 ];
__device__ __nv_bfloat16 g_wzp  [ (size_t)VAL_DIM*DIM*2 ];
__device__ __nv_bfloat16 g_woutp[ (size_t)DIM*VAL_DIM*2 ];
__device__ __nv_bfloat16 g_op   [ (size_t)MTOT*VAL_DIM*2 ];

// ================= helpers ==================================================
__device__ __forceinline__ uint32_t smem_u32(const void* p) {
    uint32_t a;
    asm("{ .reg .u64 t; cvta.to.shared.u64 t, %1; cvt.u32.u64 %0, t; }"
        : "=r"(a) : "l"(p));
    return a;
}
#define SWZ128(off) ((off) ^ (((off) >> 3) & 0x70))

#define LDMX4(r0, r1, r2, r3, addr) \
    asm volatile("ldmatrix.sync.aligned.m8n8.x4.shared.b16 {%0,%1,%2,%3}, [%4];" \
        : "=r"(r0), "=r"(r1), "=r"(r2), "=r"(r3) : "r"(addr))

#define MMA_BF16(d, a, b) \
    asm volatile("mma.sync.aligned.m16n8k16.row.col.f32.bf16.bf16.f32 " \
        "{%0,%1,%2,%3}, {%4,%5,%6,%7}, {%8,%9}, {%0,%1,%2,%3};" \
        : "+f"((d)[0]), "+f"((d)[1]), "+f"((d)[2]), "+f"((d)[3]) \
        : "r"((a)[0]), "r"((a)[1]), "r"((a)[2]), "r"((a)[3]), \
          "r"((b)[0]), "r"((b)[1]))

#define CP_ASYNC16(smem, gmem) \
    asm volatile("cp.async.cg.shared.global [%0], [%1], 16;" \
                 :: "r"(smem), "l"(gmem) : "memory")
#define CP_COMMIT() asm volatile("cp.async.commit_group;" ::: "memory")
#define CP_WAIT(n)  asm volatile("cp.async.wait_group %0;" :: "n"(n) : "memory")

__device__ __forceinline__ void split_pair(float x, float y,
                                           uint32_t& hi, uint32_t& lo) {
    __nv_bfloat16 hx = __float2bfloat16(x);
    __nv_bfloat16 hy = __float2bfloat16(y);
    __nv_bfloat162 h(hx, hy);
    hi = *reinterpret_cast<uint32_t*>(&h);
    __nv_bfloat162 l(__float2bfloat16(x - __bfloat162float(hx)),
                     __float2bfloat16(y - __bfloat162float(hy)));
    lo = *reinterpret_cast<uint32_t*>(&l);
}

// ------------- pack: fp32 [R][K] -> bf16 hi/lo rows of 128B ------------------
__global__ void __launch_bounds__(256) pack_kernel(const float* __restrict__ X,
                                                   __nv_bfloat16* __restrict__ Xp,
                                                   int K)
{
    const int idx = blockIdx.x * 256 + threadIdx.x;
    const int kq  = K >> 2;
    const int r   = idx / kq;
    const int k0  = (idx - r * kq) * 4;
    const int kt  = k0 >> 5;
    const int j   = k0 & 31;
    float4 v = *(const float4*)&X[(size_t)r * K + k0];
    uint32_t h0, l0, h1, l1;
    split_pair(v.x, v.y, h0, l0);
    split_pair(v.z, v.w, h1, l1);
    size_t base = ((size_t)r * (K >> 5) + kt) * 64 + j;
    *(uint2*)&Xp[base]      = make_uint2(h0, h1);
    *(uint2*)&Xp[base + 32] = make_uint2(l0, l1);
}

// ========== bf16x3 GEMM, CTA 128x256, 512 threads, 4x32k stages =============
// stage = 48KB: [A 16KB | B 32KB]; 2 stages in flight (CP_WAIT(2))
#define STG_A 16384
#define STG_BYTES 49152
#define GEMM_SMEM (4*STG_BYTES + 256)
#define GTHREADS 512

template<int KC>
__device__ __forceinline__ void gemm_body(const __nv_bfloat16* __restrict__ Ap,
                                          const __nv_bfloat16* __restrict__ Bp,
                                          float* __restrict__ C,
                                          int N, int bm, int bn, char* sm)
{
    const int tid  = threadIdx.x;          // 0..511
    const int lane = tid & 31;
    const int wid  = tid >> 5;             // 0..15
    const int wm = wid & 3;                // 4 m groups of 32 rows
    const int wn = wid >> 2;               // 4 n groups of 64 cols
    const uint32_t smb = (smem_u32(sm) + 127u) & ~127u;
    constexpr int KT = KC >> 5;            // 32-k tiles

    // cp.async: thread handles row rr (A) / rows rr, rr+128 (B), two 16B cols
    const int rr = tid >> 2;               // 0..127
    const int c0 = (tid & 3) * 16;
    const uint32_t sO0 = SWZ128((uint32_t)(rr*128 + c0));
    const uint32_t sO1 = SWZ128((uint32_t)(rr*128 + c0 + 64));
    const char* ApR  = (const char*)Ap + ((size_t)bm*128 + rr) * (size_t)KT * 128 + c0;
    const char* BpR0 = (const char*)Bp + ((size_t)bn*256 + rr) * (size_t)KT * 128 + c0;
    const char* BpR1 = (const char*)Bp + ((size_t)bn*256 + rr + 128) * (size_t)KT * 128 + c0;

    const int lrow = ((lane >> 3) & 1) * 8 + (lane & 7);
    const int lkof = (lane >> 4) * 8;

    float acc[2][8][4];
#pragma unroll
    for (int i = 0; i < 2; ++i)
#pragma unroll
        for (int j = 0; j < 8; ++j)
#pragma unroll
            for (int r = 0; r < 4; ++r) acc[i][j][r] = 0.f;

    auto issue_stage = [&](int kt, uint32_t sbase) {
        CP_ASYNC16(sbase + sO0,                   ApR  + (size_t)kt*128);
        CP_ASYNC16(sbase + sO1,                   ApR  + (size_t)kt*128 + 64);
        CP_ASYNC16(sbase + STG_A + sO0,           BpR0 + (size_t)kt*128);
        CP_ASYNC16(sbase + STG_A + sO1,           BpR0 + (size_t)kt*128 + 64);
        CP_ASYNC16(sbase + STG_A + 16384 + sO0,   BpR1 + (size_t)kt*128);
        CP_ASYNC16(sbase + STG_A + 16384 + sO1,   BpR1 + (size_t)kt*128 + 64);
    };

    // prologue: 3 stages in flight
#pragma unroll
    for (int s = 0; s < 3; ++s) {
        issue_stage(s, smb + s * STG_BYTES);
        CP_COMMIT();
    }

    for (int kt = 0; kt < KT; ++kt) {
        CP_WAIT(2);
        __syncthreads();

        if (kt + 3 < KT) issue_stage(kt + 3, smb + ((kt + 3) & 3) * STG_BYTES);
        CP_COMMIT();

        const uint32_t sa = smb + (kt & 3) * STG_BYTES;
        const uint32_t sb = sa + STG_A;
#pragma unroll
        for (int ks = 0; ks < 32; ks += 16) {
            uint32_t ah[2][4], al[2][4];
#pragma unroll
            for (int mt = 0; mt < 2; ++mt) {
                uint32_t pre = (uint32_t)((wm*32 + mt*16 + lrow)*128 + (ks + lkof)*2);
                uint32_t swz = SWZ128(pre);
                LDMX4(ah[mt][0], ah[mt][1], ah[mt][2], ah[mt][3], sa + swz);
                LDMX4(al[mt][0], al[mt][1], al[mt][2], al[mt][3], sa + (swz^64));
            }
            uint32_t bh[8][2], bl[8][2];
#pragma unroll
            for (int g = 0; g < 4; ++g) {
                uint32_t pre = (uint32_t)((wn*64 + g*16 + lrow)*128 + (ks + lkof)*2);
                uint32_t swz = SWZ128(pre);
                uint32_t t0, t1, t2, t3;
                LDMX4(t0, t1, t2, t3, sb + swz);
                bh[2*g][0] = t0; bh[2*g][1] = t2;
                bh[2*g+1][0] = t1; bh[2*g+1][1] = t3;
                LDMX4(t0, t1, t2, t3, sb + (swz^64));
                bl[2*g][0] = t0; bl[2*g][1] = t2;
                bl[2*g+1][0] = t1; bl[2*g+1][1] = t3;
            }
            // term-major ordering: accumulator reuse separated by 15 MMAs
#pragma unroll
            for (int nt = 0; nt < 8; ++nt) {
                MMA_BF16(acc[0][nt], ah[0], bh[nt]);
                MMA_BF16(acc[1][nt], ah[1], bh[nt]);
            }
#pragma unroll
            for (int nt = 0; nt < 8; ++nt) {
                MMA_BF16(acc[0][nt], ah[0], bl[nt]);
                MMA_BF16(acc[1][nt], ah[1], bl[nt]);
            }
#pragma unroll
            for (int nt = 0; nt < 8; ++nt) {
                MMA_BF16(acc[0][nt], al[0], bh[nt]);
                MMA_BF16(acc[1][nt], al[1], bh[nt]);
            }
        }
    }

    const int m0 = bm*128 + wm*32 + (lane >> 2);
    const int n0 = bn*256 + wn*64 + 2*(lane & 3);
#pragma unroll
    for (int mt = 0; mt < 2; ++mt)
#pragma unroll
        for (int nt = 0; nt < 8; ++nt) {
            float* c0p = C + (size_t)(m0 + mt*16) * N + n0 + nt*8;
            *(float2*)c0p = make_float2(acc[mt][nt][0], acc[mt][nt][1]);
            float* c1p = c0p + (size_t)8 * N;
            *(float2*)c1p = make_float2(acc[mt][nt][2], acc[mt][nt][3]);
        }
}

// merged qkv+z projection: bn 0..31 -> qkv, 32..47 -> z
__global__ void __launch_bounds__(GTHREADS, 1) gemm_qkvz(const __nv_bfloat16* __restrict__ xp,
                                                         const __nv_bfloat16* __restrict__ wqkvp,
                                                         const __nv_bfloat16* __restrict__ wzp,
                                                         float* __restrict__ qkv,
                                                         float* __restrict__ z)
{
    extern __shared__ char sm[];
    const int bn = blockIdx.x;
    if (bn < CONV_DIM/256)
        gemm_body<DIM>(xp, wqkvp, qkv, CONV_DIM, blockIdx.y, bn, sm);
    else
        gemm_body<DIM>(xp, wzp, z, VAL_DIM, blockIdx.y, bn - CONV_DIM/256, sm);
}

__global__ void __launch_bounds__(GTHREADS, 1) gemm_out(const __nv_bfloat16* __restrict__ Ap,
                                                        const __nv_bfloat16* __restrict__ Bp,
                                                        float* __restrict__ C)
{
    extern __shared__ char sm[];
    gemm_body<VAL_DIM>(Ap, Bp, C, DIM, blockIdx.y, blockIdx.x, sm);
}

// ------------- small GEMM for a/b + fused g/beta epilogue -------------------
__global__ void __launch_bounds__(256) ab_gemm(const float* __restrict__ x,
                                               const float* __restrict__ Wa,
                                               const float* __restrict__ Wb,
                                               const float* __restrict__ A_log,
                                               const float* __restrict__ dt_bias,
                                               float* __restrict__ eg_out,
                                               float* __restrict__ beta_out)
{
    __shared__ float xs[16][65];
    __shared__ float ws[64][65];
    const int tid = threadIdx.x;
    const int m0  = blockIdx.x * 16;

    float acc[4] = {0.f, 0.f, 0.f, 0.f};
    const int r  = tid & 15;
    const int jg = tid >> 4;

    for (int k0 = 0; k0 < DIM; k0 += 64) {
        {
            int rr = tid >> 4;
            int cc = (tid & 15) * 4;
            float4 v = *(const float4*)&x[(size_t)(m0+rr)*DIM + k0 + cc];
            xs[rr][cc] = v.x; xs[rr][cc+1] = v.y; xs[rr][cc+2] = v.z; xs[rr][cc+3] = v.w;
        }
#pragma unroll
        for (int u = 0; u < 4; ++u) {
            int idx = tid + u*256;
            int j  = idx >> 4;
            int cc = (idx & 15) * 4;
            const float* W = (j < 32) ? &Wa[(size_t)j*DIM] : &Wb[(size_t)(j-32)*DIM];
            float4 v = *(const float4*)&W[k0 + cc];
            ws[j][cc] = v.x; ws[j][cc+1] = v.y; ws[j][cc+2] = v.z; ws[j][cc+3] = v.w;
        }
        __syncthreads();
#pragma unroll 8
        for (int k = 0; k < 64; ++k) {
            float xv = xs[r][k];
            acc[0] += xv * ws[jg*4+0][k];
            acc[1] += xv * ws[jg*4+1][k];
            acc[2] += xv * ws[jg*4+2][k];
            acc[3] += xv * ws[jg*4+3][k];
        }
        __syncthreads();
    }
    const int m = m0 + r;
#pragma unroll
    for (int u = 0; u < 4; ++u) {
        int j = jg*4 + u;
        float v = acc[u];
        if (j < 32) {
            float sp = v + dt_bias[j];
            sp = (sp > 20.f) ? sp : log1pf(expf(sp));
            eg_out[(size_t)m*HV + j] = expf(-expf(A_log[j]) * sp);
        } else {
            beta_out[(size_t)m*HV + (j-32)] = 1.f / (1.f + expf(-v));
        }
    }
}

// ------------- depthwise causal conv (K=4) + SiLU ---------------------------
__global__ void __launch_bounds__(256) conv_silu_kernel(const float* __restrict__ in,
                                                        float* __restrict__ out,
                                                        const float* __restrict__ w)
{
    const int c  = blockIdx.x * 256 + threadIdx.x;
    const int lc = blockIdx.y;
    const int b  = blockIdx.z;
    const float w0 = w[c*4+0], w1 = w[c*4+1], w2 = w[c*4+2], w3 = w[c*4+3];
    const float* ip = in  + (size_t)b*LL*CONV_DIM + c;
    float*       op = out + (size_t)b*LL*CONV_DIM + c;
    const int l0 = lc * 128;
    float xm3, xm2, xm1;
    if (l0 == 0) { xm3 = xm2 = xm1 = 0.f; }
    else {
        xm3 = ip[(size_t)(l0-3)*CONV_DIM];
        xm2 = ip[(size_t)(l0-2)*CONV_DIM];
        xm1 = ip[(size_t)(l0-1)*CONV_DIM];
    }
#pragma unroll 4
    for (int l = l0; l < l0 + 128; ++l) {
        float x0 = ip[(size_t)l*CONV_DIM];
        float h = xm3*w0 + xm2*w1 + xm1*w2 + x0*w3;
        h = h / (1.f + expf(-h));
        op[(size_t)l*CONV_DIM] = h;
        xm3 = xm2; xm2 = xm1; xm1 = x0;
    }
}

// ------------- l2norm of q and k heads (in place) ---------------------------
__global__ void __launch_bounds__(256) qknorm_kernel(float* __restrict__ d)
{
    const int wid  = (blockIdx.x * blockDim.x + threadIdx.x) >> 5;
    const int lane = threadIdx.x & 31;
    const int h2 = wid & 31;
    const int l  = (wid >> 5) & (LL-1);
    const int b  = wid >> 16;
    float* p = d + ((size_t)(b*LL + l))*CONV_DIM + h2*128 + lane*4;
    float4 v = *(float4*)p;
    float ss = v.x*v.x + v.y*v.y + v.z*v.z + v.w*v.w;
#pragma unroll
    for (int o = 16; o; o >>= 1) ss += __shfl_xor_sync(0xffffffffu, ss, o);
    float r = rsqrtf(ss + 1e-6f);
    if (h2 < 16) r *= 0.08838834764831845f;
    v.x *= r; v.y *= r; v.z *= r; v.w *= r;
    *(float4*)p = v;
}

// ------------- gated delta rule scan ----------------------------------------
__global__ void __launch_bounds__(256, 1) scan_kernel(const float* __restrict__ qkv,
                                                      const float* __restrict__ eg,
                                                      const float* __restrict__ beta,
                                                      float* __restrict__ o)
{
    const int bi = blockIdx.x;
    const int vh = bi & 1;
    const int h  = (bi >> 1) & 31;
    const int b  = bi >> 6;
    const int hk = h >> 1;
    const int t  = threadIdx.x;
    const int kq   = t & 3;
    const int vloc = t >> 2;
    const int vcol = vh*64 + vloc;

    __shared__ float kq_s[2][256];
    __shared__ float egs[LL];
    __shared__ float bets[LL];

    for (int i = t; i < LL; i += 256) {
        egs[i]  = eg  [(size_t)(b*LL + i)*HV + h];
        bets[i] = beta[(size_t)(b*LL + i)*HV + h];
    }

    float s[32];
#pragma unroll
    for (int i = 0; i < 32; ++i) s[i] = 0.f;

    const float* base = qkv + (size_t)b*LL*CONV_DIM;
    const int kqoff = (t < 128) ? (KEY_DIM + hk*128 + t)
                                : (hk*128 + (t-128));
    const int voff  = 2*KEY_DIM + h*128 + vcol;
    float* optr = o + (size_t)b*LL*VAL_DIM + h*128 + vcol;

    kq_s[0][t] = base[kqoff];
    float vcur = base[voff];
    __syncthreads();

    int p = 0;
    for (int l = 0; l < LL; ++l) {
        float kqn = 0.f, vn = 0.f;
        if (l + 1 < LL) {
            kqn = base[(size_t)(l+1)*CONV_DIM + kqoff];
            vn  = base[(size_t)(l+1)*CONV_DIM + voff];
        }
        const float egv = egs[l];
        const float bv  = bets[l];
        const float* ks = &kq_s[p][kq*32];
        const float* qs = &kq_s[p][128 + kq*32];

        float kv0 = 0.f, kv1 = 0.f, kv2 = 0.f, kv3 = 0.f;
#pragma unroll
        for (int i = 0; i < 8; ++i) {
            kv0 += ks[i]    * s[i];
            kv1 += ks[i+8]  * s[i+8];
            kv2 += ks[i+16] * s[i+16];
            kv3 += ks[i+24] * s[i+24];
        }
        float kv = (kv0 + kv1) + (kv2 + kv3);
        kv += __shfl_xor_sync(0xffffffffu, kv, 1);
        kv += __shfl_xor_sync(0xffffffffu, kv, 2);
        kv *= egv;
        const float delta = (vcur - kv) * bv;

        float o0 = 0.f, o1 = 0.f, o2 = 0.f, o3 = 0.f;
#pragma unroll
        for (int i = 0; i < 8; ++i) {
            s[i]    = egv*s[i]    + ks[i]*delta;    o0 += qs[i]*s[i];
            s[i+8]  = egv*s[i+8]  + ks[i+8]*delta;  o1 += qs[i+8]*s[i+8];
            s[i+16] = egv*s[i+16] + ks[i+16]*delta; o2 += qs[i+16]*s[i+16];
            s[i+24] = egv*s[i+24] + ks[i+24]*delta; o3 += qs[i+24]*s[i+24];
        }
        float outv = (o0 + o1) + (o2 + o3);
        outv += __shfl_xor_sync(0xffffffffu, outv, 1);
        outv += __shfl_xor_sync(0xffffffffu, outv, 2);
        if (kq == 0) optr[(size_t)l*VAL_DIM] = outv;

        kq_s[p^1][t] = kqn;
        vcur = vn;
        __syncthreads();
        p ^= 1;
    }
}

// ------------- gated RMSNorm + pack to bf16 hi/lo ---------------------------
__global__ void __launch_bounds__(256) rmsgate_pack_kernel(const float* __restrict__ o,
                                                           const float* __restrict__ z,
                                                           const float* __restrict__ nw,
                                                           __nv_bfloat16* __restrict__ op)
{
    const int wid  = (blockIdx.x * blockDim.x + threadIdx.x) >> 5;
    const int lane = threadIdx.x & 31;
    const float* p  = o + (size_t)wid*128 + lane*4;
    const float* zp = z + (size_t)wid*128 + lane*4;
    float4 v = *(const float4*)p;
    float ss = v.x*v.x + v.y*v.y + v.z*v.z + v.w*v.w;
#pragma unroll
    for (int off = 16; off; off >>= 1) ss += __shfl_xor_sync(0xffffffffu, ss, off);
    const float r = rsqrtf(ss * (1.f/128.f) + 1e-6f);
    float4 zv = *(const float4*)zp;
    float4 w4 = *(const float4*)&nw[lane*4];
    float4 out;
    out.x = v.x * r * w4.x * (zv.x / (1.f + expf(-zv.x)));
    out.y = v.y * r * w4.y * (zv.y / (1.f + expf(-zv.y)));
    out.z = v.z * r * w4.z * (zv.z / (1.f + expf(-zv.z)));
    out.w = v.w * r * w4.w * (zv.w / (1.f + expf(-zv.w)));
    const int m = wid >> 5;
    const int h = wid & 31;
    const int c = h*128 + lane*4;
    const int kt = c >> 5, j = c & 31;
    uint32_t h0, l0, h1, l1;
    split_pair(out.x, out.y, h0, l0);
    split_pair(out.z, out.w, h1, l1);
    size_t base = ((size_t)m * (VAL_DIM >> 5) + kt) * 64 + j;
    *(uint2*)&op[base]      = make_uint2(h0, h1);
    *(uint2*)&op[base + 32] = make_uint2(l0, l1);
}

// ---------------- launch ----------------------------------------------------
extern "C" void kernel_launch(void* const* d_in, const int* in_sizes, int n_in,
                              void* d_out, int out_size)
{
    const float* x       = (const float*)d_in[0];
    const float* W_qkv   = (const float*)d_in[1];
    const float* W_z     = (const float*)d_in[2];
    const float* W_a     = (const float*)d_in[3];
    const float* W_b     = (const float*)d_in[4];
    const float* conv_w  = (const float*)d_in[5];
    const float* A_log   = (const float*)d_in[6];
    const float* dt_bias = (const float*)d_in[7];
    const float* norm_w  = (const float*)d_in[8];
    const float* W_out   = (const float*)d_in[9];
    float* out = (float*)d_out;

    float *qkv, *cnv, *z, *eg, *bet, *o;
    __nv_bfloat16 *xp, *wqkvp, *wzp, *woutp, *op;
    cudaGetSymbolAddress((void**)&qkv, g_qkv);
    cudaGetSymbolAddress((void**)&cnv, g_conv);
    cudaGetSymbolAddress((void**)&z,   g_z);
    cudaGetSymbolAddress((void**)&eg,  g_eg);
    cudaGetSymbolAddress((void**)&bet, g_beta);
    cudaGetSymbolAddress((void**)&o,   g_o);
    cudaGetSymbolAddress((void**)&xp,    g_xp);
    cudaGetSymbolAddress((void**)&wqkvp, g_wqkvp);
    cudaGetSymbolAddress((void**)&wzp,   g_wzp);
    cudaGetSymbolAddress((void**)&woutp, g_woutp);
    cudaGetSymbolAddress((void**)&op,    g_op);

    cudaFuncSetAttribute(gemm_qkvz, cudaFuncAttributeMaxDynamicSharedMemorySize, GEMM_SMEM);
    cudaFuncSetAttribute(gemm_out,  cudaFuncAttributeMaxDynamicSharedMemorySize, GEMM_SMEM);

    // 0) packs — merged GEMM is the 4th launch (ncu capture)
    pack_kernel<<<(MTOT*DIM/4)/256, 256>>>(x, xp, DIM);
    pack_kernel<<<((size_t)CONV_DIM*DIM/4)/256, 256>>>(W_qkv, wqkvp, DIM);
    pack_kernel<<<((size_t)VAL_DIM*DIM/4)/256, 256>>>(W_z, wzp, DIM);
    // 1) merged qkv + z projection
    gemm_qkvz<<<dim3(CONV_DIM/256 + VAL_DIM/256, MTOT/128), GTHREADS, GEMM_SMEM>>>(
        xp, wqkvp, wzp, qkv, z);
    // 2) remaining pack + a/b
    pack_kernel<<<((size_t)DIM*VAL_DIM/4)/256, 256>>>(W_out, woutp, VAL_DIM);
    ab_gemm<<<MTOT/16, 256>>>(x, W_a, W_b, A_log, dt_bias, eg, bet);
    // 3) conv + qknorm
    conv_silu_kernel<<<dim3(CONV_DIM/256, LL/128, BB), 256>>>(qkv, cnv, conv_w);
    qknorm_kernel<<<(BB*LL*32)/8, 256>>>(cnv);
    // 4) scan
    scan_kernel<<<BB*HV*2, 256>>>(cnv, eg, bet, o);
    // 5) gated RMSNorm + pack
    rmsgate_pack_kernel<<<(BB*LL*HV)/8, 256>>>(o, z, norm_w, op);
    // 6) output projection
    gemm_out<<<dim3(DIM/256, MTOT/128), GTHREADS, GEMM_SMEM>>>(op, woutp, out);
}

// round 13
// speedup vs baseline: 1.0108x; 1.0108x over previous
#include <cuda_runtime.h>
#include <cuda_bf16.h>
#include <math.h>
#include <cstdint>

// ---------------- problem constants ----------------
#define BB 2
#define LL 2048
#define DIM 2048
#define HK 16
#define HV 32
#define DK 128
#define DV 128
#define KCONV 4
#define KEY_DIM (HK*DK)            // 2048
#define VAL_DIM (HV*DV)            // 4096
#define CONV_DIM (2*KEY_DIM+VAL_DIM) // 8192
#define MTOT (BB*LL)               // 4096

// ---------------- scratch ----------------
__device__ float g_qkv [ (size_t)BB*LL*CONV_DIM ];
__device__ float g_conv[ (size_t)BB*LL*CONV_DIM ];
__device__ float g_z   [ (size_t)BB*LL*VAL_DIM  ];
__device__ float g_eg  [ (size_t)BB*LL*HV ];
__device__ float g_beta[ (size_t)BB*LL*HV ];
__device__ float g_o   [ (size_t)BB*LL*VAL_DIM  ];
__device__ __nv_bfloat16 g_xp   [ (size_t)MTOT*DIM*2 ];
__device__ __nv_bfloat16 g_wqkvp[ (size_t)CONV_DIM*DIM*2 ];
__device__ __nv_bfloat16 g_wzp  [ (size_t)VAL_DIM*DIM*2 ];
__device__ __nv_bfloat16 g_woutp[ (size_t)DIM*VAL_DIM*2 ];
__device__ __nv_bfloat16 g_op   [ (size_t)MTOT*VAL_DIM*2 ];

// ================= helpers ==================================================
__device__ __forceinline__ uint32_t smem_u32(const void* p) {
    uint32_t a;
    asm("{ .reg .u64 t; cvta.to.shared.u64 t, %1; cvt.u32.u64 %0, t; }"
        : "=r"(a) : "l"(p));
    return a;
}
#define SWZ128(off) ((off) ^ (((off) >> 3) & 0x70))

#define LDMX4(r0, r1, r2, r3, addr) \
    asm volatile("ldmatrix.sync.aligned.m8n8.x4.shared.b16 {%0,%1,%2,%3}, [%4];" \
        : "=r"(r0), "=r"(r1), "=r"(r2), "=r"(r3) : "r"(addr))

#define MMA_BF16(d, a, b) \
    asm volatile("mma.sync.aligned.m16n8k16.row.col.f32.bf16.bf16.f32 " \
        "{%0,%1,%2,%3}, {%4,%5,%6,%7}, {%8,%9}, {%0,%1,%2,%3};" \
        : "+f"((d)[0]), "+f"((d)[1]), "+f"((d)[2]), "+f"((d)[3]) \
        : "r"((a)[0]), "r"((a)[1]), "r"((a)[2]), "r"((a)[3]), \
          "r"((b)[0]), "r"((b)[1]))

#define CP_ASYNC16(smem, gmem) \
    asm volatile("cp.async.cg.shared.global [%0], [%1], 16;" \
                 :: "r"(smem), "l"(gmem) : "memory")
#define CP_COMMIT() asm volatile("cp.async.commit_group;" ::: "memory")
#define CP_WAIT(n)  asm volatile("cp.async.wait_group %0;" :: "n"(n) : "memory")

__device__ __forceinline__ void split_pair(float x, float y,
                                           uint32_t& hi, uint32_t& lo) {
    __nv_bfloat16 hx = __float2bfloat16(x);
    __nv_bfloat16 hy = __float2bfloat16(y);
    __nv_bfloat162 h(hx, hy);
    hi = *reinterpret_cast<uint32_t*>(&h);
    __nv_bfloat162 l(__float2bfloat16(x - __bfloat162float(hx)),
                     __float2bfloat16(y - __bfloat162float(hy)));
    lo = *reinterpret_cast<uint32_t*>(&l);
}

// ------------- pack: fp32 [R][K] -> bf16 hi/lo rows of 128B ------------------
__global__ void __launch_bounds__(256) pack_kernel(const float* __restrict__ X,
                                                   __nv_bfloat16* __restrict__ Xp,
                                                   int K)
{
    const int idx = blockIdx.x * 256 + threadIdx.x;
    const int kq  = K >> 2;
    const int r   = idx / kq;
    const int k0  = (idx - r * kq) * 4;
    const int kt  = k0 >> 5;
    const int j   = k0 & 31;
    float4 v = *(const float4*)&X[(size_t)r * K + k0];
    uint32_t h0, l0, h1, l1;
    split_pair(v.x, v.y, h0, l0);
    split_pair(v.z, v.w, h1, l1);
    size_t base = ((size_t)r * (K >> 5) + kt) * 64 + j;
    *(uint2*)&Xp[base]      = make_uint2(h0, h1);
    *(uint2*)&Xp[base + 32] = make_uint2(l0, l1);
}

// ================= bf16x3 GEMM, CTA 128x256, 512 threads, 64-k stages =======
// (EXACT R8 configuration — measured local optimum)
#define SUB_A 16384
#define SUB_B 32768
#define SUB_BYTES (SUB_A + SUB_B)        // 49152
#define STAGE_BYTES (2*SUB_BYTES)        // 98304
#define GEMM_SMEM (2*STAGE_BYTES + 256)  // NSTAGE=2
#define GTHREADS 512

__device__ __forceinline__ void gemm_k64(const __nv_bfloat16* __restrict__ Ap,
                                         const __nv_bfloat16* __restrict__ Bp,
                                         float* __restrict__ C,
                                         int N, int K, int bm, int bn, char* sm)
{
    const int tid  = threadIdx.x;          // 0..511
    const int lane = tid & 31;
    const int wid  = tid >> 5;             // 0..15
    const int wm = wid & 3;                // 4 m groups of 32 rows
    const int wn = wid >> 2;               // 4 n groups of 64 cols
    const uint32_t smb = (smem_u32(sm) + 127u) & ~127u;
    const int KT  = K >> 5;
    const int KT2 = K >> 6;

    const int r0  = tid >> 3;              // 0..63
    const int g16 = (tid & 7) * 16;
    uint32_t soffA[2], soffB[4];
#pragma unroll
    for (int q = 0; q < 2; ++q) soffA[q] = SWZ128((uint32_t)((r0 + q*64)*128 + g16));
#pragma unroll
    for (int q = 0; q < 4; ++q) soffB[q] = SWZ128((uint32_t)((r0 + q*64)*128 + g16));
    const char* Apb = (const char*)Ap + ((size_t)bm * 128) * (size_t)KT * 128;
    const char* Bpb = (const char*)Bp + ((size_t)bn * 256) * (size_t)KT * 128;

    const int lrow = ((lane >> 3) & 1) * 8 + (lane & 7);
    const int lkof = (lane >> 4) * 8;

    float acc[2][8][4];
#pragma unroll
    for (int i = 0; i < 2; ++i)
#pragma unroll
        for (int j = 0; j < 8; ++j)
#pragma unroll
            for (int r = 0; r < 4; ++r) acc[i][j][r] = 0.f;

    auto issue_stage = [&](int kt2, uint32_t sbase) {
#pragma unroll
        for (int sub = 0; sub < 2; ++sub) {
            const int kt = kt2*2 + sub;
            const uint32_t sa = sbase + sub * SUB_BYTES;
#pragma unroll
            for (int q = 0; q < 2; ++q)
                CP_ASYNC16(sa + soffA[q], Apb + ((size_t)(r0 + q*64) * KT + kt) * 128 + g16);
#pragma unroll
            for (int q = 0; q < 4; ++q)
                CP_ASYNC16(sa + SUB_A + soffB[q], Bpb + ((size_t)(r0 + q*64) * KT + kt) * 128 + g16);
        }
    };

    issue_stage(0, smb);
    CP_COMMIT();

    for (int kt2 = 0; kt2 < KT2; ++kt2) {
        CP_WAIT(0);
        __syncthreads();

        if (kt2 + 1 < KT2) issue_stage(kt2 + 1, smb + ((kt2 + 1) & 1) * STAGE_BYTES);
        CP_COMMIT();

        const uint32_t stg = smb + (kt2 & 1) * STAGE_BYTES;
#pragma unroll
        for (int sub = 0; sub < 2; ++sub) {
            const uint32_t sa = stg + sub * SUB_BYTES;
            const uint32_t sb = sa + SUB_A;
#pragma unroll
            for (int ks = 0; ks < 32; ks += 16) {
                uint32_t ah[2][4], al[2][4];
#pragma unroll
                for (int mt = 0; mt < 2; ++mt) {
                    uint32_t pre = (uint32_t)((wm*32 + mt*16 + lrow)*128 + (ks + lkof)*2);
                    uint32_t swz = SWZ128(pre);
                    LDMX4(ah[mt][0], ah[mt][1], ah[mt][2], ah[mt][3], sa + swz);
                    LDMX4(al[mt][0], al[mt][1], al[mt][2], al[mt][3], sa + (swz^64));
                }
                uint32_t bh[8][2], bl[8][2];
#pragma unroll
                for (int g = 0; g < 4; ++g) {
                    uint32_t pre = (uint32_t)((wn*64 + g*16 + lrow)*128 + (ks + lkof)*2);
                    uint32_t swz = SWZ128(pre);
                    uint32_t t0, t1, t2, t3;
                    LDMX4(t0, t1, t2, t3, sb + swz);
                    bh[2*g][0] = t0; bh[2*g][1] = t2;
                    bh[2*g+1][0] = t1; bh[2*g+1][1] = t3;
                    LDMX4(t0, t1, t2, t3, sb + (swz^64));
                    bl[2*g][0] = t0; bl[2*g][1] = t2;
                    bl[2*g+1][0] = t1; bl[2*g+1][1] = t3;
                }
                // term-major ordering: accumulator reuse separated by 15 MMAs
#pragma unroll
                for (int nt = 0; nt < 8; ++nt) {
                    MMA_BF16(acc[0][nt], ah[0], bh[nt]);
                    MMA_BF16(acc[1][nt], ah[1], bh[nt]);
                }
#pragma unroll
                for (int nt = 0; nt < 8; ++nt) {
                    MMA_BF16(acc[0][nt], ah[0], bl[nt]);
                    MMA_BF16(acc[1][nt], ah[1], bl[nt]);
                }
#pragma unroll
                for (int nt = 0; nt < 8; ++nt) {
                    MMA_BF16(acc[0][nt], al[0], bh[nt]);
                    MMA_BF16(acc[1][nt], al[1], bh[nt]);
                }
            }
        }
    }

    const int m0 = bm*128 + wm*32 + (lane >> 2);
    const int n0 = bn*256 + wn*64 + 2*(lane & 3);
#pragma unroll
    for (int mt = 0; mt < 2; ++mt)
#pragma unroll
        for (int nt = 0; nt < 8; ++nt) {
            float* c0 = C + (size_t)(m0 + mt*16) * N + n0 + nt*8;
            *(float2*)c0 = make_float2(acc[mt][nt][0], acc[mt][nt][1]);
            float* c1 = c0 + (size_t)8 * N;
            *(float2*)c1 = make_float2(acc[mt][nt][2], acc[mt][nt][3]);
        }
}

// merged qkv+z projection: bn 0..31 -> qkv, 32..47 -> z
__global__ void __launch_bounds__(GTHREADS, 1) gemm_qkvz(const __nv_bfloat16* __restrict__ xp,
                                                         const __nv_bfloat16* __restrict__ wqkvp,
                                                         const __nv_bfloat16* __restrict__ wzp,
                                                         float* __restrict__ qkv,
                                                         float* __restrict__ z)
{
    extern __shared__ char sm[];
    const int bn = blockIdx.x;
    if (bn < CONV_DIM/256)
        gemm_k64(xp, wqkvp, qkv, CONV_DIM, DIM, blockIdx.y, bn, sm);
    else
        gemm_k64(xp, wzp, z, VAL_DIM, DIM, blockIdx.y, bn - CONV_DIM/256, sm);
}

__global__ void __launch_bounds__(GTHREADS, 1) gemm_single(const __nv_bfloat16* __restrict__ Ap,
                                                           const __nv_bfloat16* __restrict__ Bp,
                                                           float* __restrict__ C,
                                                           int N, int K)
{
    extern __shared__ char sm[];
    gemm_k64(Ap, Bp, C, N, K, blockIdx.y, blockIdx.x, sm);
}

// ------------- small GEMM for a/b + fused g/beta epilogue -------------------
__global__ void __launch_bounds__(256) ab_gemm(const float* __restrict__ x,
                                               const float* __restrict__ Wa,
                                               const float* __restrict__ Wb,
                                               const float* __restrict__ A_log,
                                               const float* __restrict__ dt_bias,
                                               float* __restrict__ eg_out,
                                               float* __restrict__ beta_out)
{
    __shared__ float xs[16][65];
    __shared__ float ws[64][65];
    const int tid = threadIdx.x;
    const int m0  = blockIdx.x * 16;

    float acc[4] = {0.f, 0.f, 0.f, 0.f};
    const int r  = tid & 15;
    const int jg = tid >> 4;

    for (int k0 = 0; k0 < DIM; k0 += 64) {
        {
            int rr = tid >> 4;
            int cc = (tid & 15) * 4;
            float4 v = *(const float4*)&x[(size_t)(m0+rr)*DIM + k0 + cc];
            xs[rr][cc] = v.x; xs[rr][cc+1] = v.y; xs[rr][cc+2] = v.z; xs[rr][cc+3] = v.w;
        }
#pragma unroll
        for (int u = 0; u < 4; ++u) {
            int idx = tid + u*256;
            int j  = idx >> 4;
            int cc = (idx & 15) * 4;
            const float* W = (j < 32) ? &Wa[(size_t)j*DIM] : &Wb[(size_t)(j-32)*DIM];
            float4 v = *(const float4*)&W[k0 + cc];
            ws[j][cc] = v.x; ws[j][cc+1] = v.y; ws[j][cc+2] = v.z; ws[j][cc+3] = v.w;
        }
        __syncthreads();
#pragma unroll 8
        for (int k = 0; k < 64; ++k) {
            float xv = xs[r][k];
            acc[0] += xv * ws[jg*4+0][k];
            acc[1] += xv * ws[jg*4+1][k];
            acc[2] += xv * ws[jg*4+2][k];
            acc[3] += xv * ws[jg*4+3][k];
        }
        __syncthreads();
    }
    const int m = m0 + r;
#pragma unroll
    for (int u = 0; u < 4; ++u) {
        int j = jg*4 + u;
        float v = acc[u];
        if (j < 32) {
            float sp = v + dt_bias[j];
            sp = (sp > 20.f) ? sp : log1pf(expf(sp));
            eg_out[(size_t)m*HV + j] = expf(-expf(A_log[j]) * sp);
        } else {
            beta_out[(size_t)m*HV + (j-32)] = 1.f / (1.f + expf(-v));
        }
    }
}

// ------------- depthwise causal conv (K=4) + SiLU ---------------------------
__global__ void __launch_bounds__(256) conv_silu_kernel(const float* __restrict__ in,
                                                        float* __restrict__ out,
                                                        const float* __restrict__ w)
{
    const int c  = blockIdx.x * 256 + threadIdx.x;
    const int lc = blockIdx.y;
    const int b  = blockIdx.z;
    const float w0 = w[c*4+0], w1 = w[c*4+1], w2 = w[c*4+2], w3 = w[c*4+3];
    const float* ip = in  + (size_t)b*LL*CONV_DIM + c;
    float*       op = out + (size_t)b*LL*CONV_DIM + c;
    const int l0 = lc * 128;
    float xm3, xm2, xm1;
    if (l0 == 0) { xm3 = xm2 = xm1 = 0.f; }
    else {
        xm3 = ip[(size_t)(l0-3)*CONV_DIM];
        xm2 = ip[(size_t)(l0-2)*CONV_DIM];
        xm1 = ip[(size_t)(l0-1)*CONV_DIM];
    }
#pragma unroll 4
    for (int l = l0; l < l0 + 128; ++l) {
        float x0 = ip[(size_t)l*CONV_DIM];
        float h = xm3*w0 + xm2*w1 + xm1*w2 + x0*w3;
        h = h / (1.f + expf(-h));
        op[(size_t)l*CONV_DIM] = h;
        xm3 = xm2; xm2 = xm1; xm1 = x0;
    }
}

// ------------- l2norm of q and k heads (in place) ---------------------------
__global__ void __launch_bounds__(256) qknorm_kernel(float* __restrict__ d)
{
    const int wid  = (blockIdx.x * blockDim.x + threadIdx.x) >> 5;
    const int lane = threadIdx.x & 31;
    const int h2 = wid & 31;
    const int l  = (wid >> 5) & (LL-1);
    const int b  = wid >> 16;
    float* p = d + ((size_t)(b*LL + l))*CONV_DIM + h2*128 + lane*4;
    float4 v = *(float4*)p;
    float ss = v.x*v.x + v.y*v.y + v.z*v.z + v.w*v.w;
#pragma unroll
    for (int o = 16; o; o >>= 1) ss += __shfl_xor_sync(0xffffffffu, ss, o);
    float r = rsqrtf(ss + 1e-6f);
    if (h2 < 16) r *= 0.08838834764831845f;
    v.x *= r; v.y *= r; v.z *= r; v.w *= r;
    *(float4*)p = v;
}

// ------------- gated delta rule scan (2-deep global prefetch) ----------------
__global__ void __launch_bounds__(256, 1) scan_kernel(const float* __restrict__ qkv,
                                                      const float* __restrict__ eg,
                                                      const float* __restrict__ beta,
                                                      float* __restrict__ o)
{
    const int bi = blockIdx.x;
    const int vh = bi & 1;
    const int h  = (bi >> 1) & 31;
    const int b  = bi >> 6;
    const int hk = h >> 1;
    const int t  = threadIdx.x;
    const int kq   = t & 3;
    const int vloc = t >> 2;
    const int vcol = vh*64 + vloc;

    __shared__ float kq_s[2][256];
    __shared__ float egs[LL];
    __shared__ float bets[LL];

    for (int i = t; i < LL; i += 256) {
        egs[i]  = eg  [(size_t)(b*LL + i)*HV + h];
        bets[i] = beta[(size_t)(b*LL + i)*HV + h];
    }

    float s[32];
#pragma unroll
    for (int i = 0; i < 32; ++i) s[i] = 0.f;

    const float* base = qkv + (size_t)b*LL*CONV_DIM;
    const int kqoff = (t < 128) ? (KEY_DIM + hk*128 + t)
                                : (hk*128 + (t-128));
    const int voff  = 2*KEY_DIM + h*128 + vcol;
    float* optr = o + (size_t)b*LL*VAL_DIM + h*128 + vcol;

    // prologue: data for l=0 (smem) and l=1 (regs)
    kq_s[0][t] = base[kqoff];
    float vcur = base[voff];
    float kqn  = base[(size_t)CONV_DIM + kqoff];
    float vn   = base[(size_t)CONV_DIM + voff];
    __syncthreads();

    int p = 0;
    for (int l = 0; l < LL; ++l) {
        // issue loads for l+2 (two iterations of slack vs L2 latency)
        float kqn2 = 0.f, vn2 = 0.f;
        if (l + 2 < LL) {
            kqn2 = base[(size_t)(l+2)*CONV_DIM + kqoff];
            vn2  = base[(size_t)(l+2)*CONV_DIM + voff];
        }
        // store l+1's k/q into the other buffer early (sync at loop end covers it)
        kq_s[p^1][t] = kqn;

        const float egv = egs[l];
        const float bv  = bets[l];
        const float* ks = &kq_s[p][kq*32];
        const float* qs = &kq_s[p][128 + kq*32];

        float kv0 = 0.f, kv1 = 0.f, kv2 = 0.f, kv3 = 0.f;
#pragma unroll
        for (int i = 0; i < 8; ++i) {
            kv0 += ks[i]    * s[i];
            kv1 += ks[i+8]  * s[i+8];
            kv2 += ks[i+16] * s[i+16];
            kv3 += ks[i+24] * s[i+24];
        }
        float kv = (kv0 + kv1) + (kv2 + kv3);
        kv += __shfl_xor_sync(0xffffffffu, kv, 1);
        kv += __shfl_xor_sync(0xffffffffu, kv, 2);
        kv *= egv;
        const float delta = (vcur - kv) * bv;

        float o0 = 0.f, o1 = 0.f, o2 = 0.f, o3 = 0.f;
#pragma unroll
        for (int i = 0; i < 8; ++i) {
            s[i]    = egv*s[i]    + ks[i]*delta;    o0 += qs[i]*s[i];
            s[i+8]  = egv*s[i+8]  + ks[i+8]*delta;  o1 += qs[i+8]*s[i+8];
            s[i+16] = egv*s[i+16] + ks[i+16]*delta; o2 += qs[i+16]*s[i+16];
            s[i+24] = egv*s[i+24] + ks[i+24]*delta; o3 += qs[i+24]*s[i+24];
        }
        float outv = (o0 + o1) + (o2 + o3);
        outv += __shfl_xor_sync(0xffffffffu, outv, 1);
        outv += __shfl_xor_sync(0xffffffffu, outv, 2);
        if (kq == 0) optr[(size_t)l*VAL_DIM] = outv;

        vcur = vn;
        kqn  = kqn2;
        vn   = vn2;
        __syncthreads();
        p ^= 1;
    }
}

// ------------- gated RMSNorm + pack to bf16 hi/lo ---------------------------
__global__ void __launch_bounds__(256) rmsgate_pack_kernel(const float* __restrict__ o,
                                                           const float* __restrict__ z,
                                                           const float* __restrict__ nw,
                                                           __nv_bfloat16* __restrict__ op)
{
    const int wid  = (blockIdx.x * blockDim.x + threadIdx.x) >> 5;
    const int lane = threadIdx.x & 31;
    const float* p  = o + (size_t)wid*128 + lane*4;
    const float* zp = z + (size_t)wid*128 + lane*4;
    float4 v = *(const float4*)p;
    float ss = v.x*v.x + v.y*v.y + v.z*v.z + v.w*v.w;
#pragma unroll
    for (int off = 16; off; off >>= 1) ss += __shfl_xor_sync(0xffffffffu, ss, off);
    const float r = rsqrtf(ss * (1.f/128.f) + 1e-6f);
    float4 zv = *(const float4*)zp;
    float4 w4 = *(const float4*)&nw[lane*4];
    float4 out;
    out.x = v.x * r * w4.x * (zv.x / (1.f + expf(-zv.x)));
    out.y = v.y * r * w4.y * (zv.y / (1.f + expf(-zv.y)));
    out.z = v.z * r * w4.z * (zv.z / (1.f + expf(-zv.z)));
    out.w = v.w * r * w4.w * (zv.w / (1.f + expf(-zv.w)));
    const int m = wid >> 5;
    const int h = wid & 31;
    const int c = h*128 + lane*4;
    const int kt = c >> 5, j = c & 31;
    uint32_t h0, l0, h1, l1;
    split_pair(out.x, out.y, h0, l0);
    split_pair(out.z, out.w, h1, l1);
    size_t base = ((size_t)m * (VAL_DIM >> 5) + kt) * 64 + j;
    *(uint2*)&op[base]      = make_uint2(h0, h1);
    *(uint2*)&op[base + 32] = make_uint2(l0, l1);
}

// ---------------- launch ----------------------------------------------------
extern "C" void kernel_launch(void* const* d_in, const int* in_sizes, int n_in,
                              void* d_out, int out_size)
{
    const float* x       = (const float*)d_in[0];
    const float* W_qkv   = (const float*)d_in[1];
    const float* W_z     = (const float*)d_in[2];
    const float* W_a     = (const float*)d_in[3];
    const float* W_b     = (const float*)d_in[4];
    const float* conv_w  = (const float*)d_in[5];
    const float* A_log   = (const float*)d_in[6];
    const float* dt_bias = (const float*)d_in[7];
    const float* norm_w  = (const float*)d_in[8];
    const float* W_out   = (const float*)d_in[9];
    float* out = (float*)d_out;

    float *qkv, *cnv, *z, *eg, *bet, *o;
    __nv_bfloat16 *xp, *wqkvp, *wzp, *woutp, *op;
    cudaGetSymbolAddress((void**)&qkv, g_qkv);
    cudaGetSymbolAddress((void**)&cnv, g_conv);
    cudaGetSymbolAddress((void**)&z,   g_z);
    cudaGetSymbolAddress((void**)&eg,  g_eg);
    cudaGetSymbolAddress((void**)&bet, g_beta);
    cudaGetSymbolAddress((void**)&o,   g_o);
    cudaGetSymbolAddress((void**)&xp,    g_xp);
    cudaGetSymbolAddress((void**)&wqkvp, g_wqkvp);
    cudaGetSymbolAddress((void**)&wzp,   g_wzp);
    cudaGetSymbolAddress((void**)&woutp, g_woutp);
    cudaGetSymbolAddress((void**)&op,    g_op);

    cudaFuncSetAttribute(gemm_qkvz,   cudaFuncAttributeMaxDynamicSharedMemorySize, GEMM_SMEM);
    cudaFuncSetAttribute(gemm_single, cudaFuncAttributeMaxDynamicSharedMemorySize, GEMM_SMEM);

    // 0) packs — merged GEMM is the 4th launch (ncu capture)
    pack_kernel<<<(MTOT*DIM/4)/256, 256>>>(x, xp, DIM);
    pack_kernel<<<((size_t)CONV_DIM*DIM/4)/256, 256>>>(W_qkv, wqkvp, DIM);
    pack_kernel<<<((size_t)VAL_DIM*DIM/4)/256, 256>>>(W_z, wzp, DIM);
    // 1) merged qkv + z projection
    gemm_qkvz<<<dim3(CONV_DIM/256 + VAL_DIM/256, MTOT/128), GTHREADS, GEMM_SMEM>>>(
        xp, wqkvp, wzp, qkv, z);
    // 2) remaining pack + a/b
    pack_kernel<<<((size_t)DIM*VAL_DIM/4)/256, 256>>>(W_out, woutp, VAL_DIM);
    ab_gemm<<<MTOT/16, 256>>>(x, W_a, W_b, A_log, dt_bias, eg, bet);
    // 3) conv + qknorm
    conv_silu_kernel<<<dim3(CONV_DIM/256, LL/128, BB), 256>>>(qkv, cnv, conv_w);
    qknorm_kernel<<<(BB*LL*32)/8, 256>>>(cnv);
    // 4) scan
    scan_kernel<<<BB*HV*2, 256>>>(cnv, eg, bet, o);
    // 5) gated RMSNorm + pack
    rmsgate_pack_kernel<<<(BB*LL*HV)/8, 256>>>(o, z, norm_w, op);
    // 6) output projection
    gemm_single<<<dim3(DIM/256, MTOT/128), GTHREADS, GEMM_SMEM>>>(op, woutp, out, DIM, VAL_DIM);
}

// round 14
// speedup vs baseline: 1.0389x; 1.0278x over previous
#include <cuda_runtime.h>
#include <cuda_bf16.h>
#include <math.h>
#include <cstdint>

// ---------------- problem constants ----------------
#define BB 2
#define LL 2048
#define DIM 2048
#define HK 16
#define HV 32
#define DK 128
#define DV 128
#define KCONV 4
#define KEY_DIM (HK*DK)            // 2048
#define VAL_DIM (HV*DV)            // 4096
#define CONV_DIM (2*KEY_DIM+VAL_DIM) // 8192
#define MTOT (BB*LL)               // 4096

// ---------------- scratch ----------------
__device__ float g_qkv [ (size_t)BB*LL*CONV_DIM ];
__device__ float g_conv[ (size_t)BB*LL*CONV_DIM ];
__device__ float g_z   [ (size_t)BB*LL*VAL_DIM  ];
__device__ float g_eg  [ (size_t)BB*LL*HV ];
__device__ float g_beta[ (size_t)BB*LL*HV ];
__device__ float g_o   [ (size_t)BB*LL*VAL_DIM  ];
__device__ __nv_bfloat16 g_xp   [ (size_t)MTOT*DIM*2 ];
__device__ __nv_bfloat16 g_wqkvp[ (size_t)CONV_DIM*DIM*2 ];
__device__ __nv_bfloat16 g_wzp  [ (size_t)VAL_DIM*DIM*2 ];
__device__ __nv_bfloat16 g_woutp[ (size_t)DIM*VAL_DIM*2 ];
__device__ __nv_bfloat16 g_op   [ (size_t)MTOT*VAL_DIM*2 ];

// ================= helpers ==================================================
__device__ __forceinline__ uint32_t smem_u32(const void* p) {
    uint32_t a;
    asm("{ .reg .u64 t; cvta.to.shared.u64 t, %1; cvt.u32.u64 %0, t; }"
        : "=r"(a) : "l"(p));
    return a;
}
#define SWZ128(off) ((off) ^ (((off) >> 3) & 0x70))

#define LDMX4(r0, r1, r2, r3, addr) \
    asm volatile("ldmatrix.sync.aligned.m8n8.x4.shared.b16 {%0,%1,%2,%3}, [%4];" \
        : "=r"(r0), "=r"(r1), "=r"(r2), "=r"(r3) : "r"(addr))

#define MMA_BF16(d, a, b) \
    asm volatile("mma.sync.aligned.m16n8k16.row.col.f32.bf16.bf16.f32 " \
        "{%0,%1,%2,%3}, {%4,%5,%6,%7}, {%8,%9}, {%0,%1,%2,%3};" \
        : "+f"((d)[0]), "+f"((d)[1]), "+f"((d)[2]), "+f"((d)[3]) \
        : "r"((a)[0]), "r"((a)[1]), "r"((a)[2]), "r"((a)[3]), \
          "r"((b)[0]), "r"((b)[1]))

#define CP_ASYNC16(smem, gmem) \
    asm volatile("cp.async.cg.shared.global [%0], [%1], 16;" \
                 :: "r"(smem), "l"(gmem) : "memory")
#define CP_COMMIT() asm volatile("cp.async.commit_group;" ::: "memory")
#define CP_WAIT(n)  asm volatile("cp.async.wait_group %0;" :: "n"(n) : "memory")

__device__ __forceinline__ void split_pair(float x, float y,
                                           uint32_t& hi, uint32_t& lo) {
    __nv_bfloat16 hx = __float2bfloat16(x);
    __nv_bfloat16 hy = __float2bfloat16(y);
    __nv_bfloat162 h(hx, hy);
    hi = *reinterpret_cast<uint32_t*>(&h);
    __nv_bfloat162 l(__float2bfloat16(x - __bfloat162float(hx)),
                     __float2bfloat16(y - __bfloat162float(hy)));
    lo = *reinterpret_cast<uint32_t*>(&l);
}

// ------------- pack: fp32 [R][K] -> bf16 hi/lo rows of 128B ------------------
__global__ void __launch_bounds__(256) pack_kernel(const float* __restrict__ X,
                                                   __nv_bfloat16* __restrict__ Xp,
                                                   int K)
{
    const int idx = blockIdx.x * 256 + threadIdx.x;
    const int kq  = K >> 2;
    const int r   = idx / kq;
    const int k0  = (idx - r * kq) * 4;
    const int kt  = k0 >> 5;
    const int j   = k0 & 31;
    float4 v = *(const float4*)&X[(size_t)r * K + k0];
    uint32_t h0, l0, h1, l1;
    split_pair(v.x, v.y, h0, l0);
    split_pair(v.z, v.w, h1, l1);
    size_t base = ((size_t)r * (K >> 5) + kt) * 64 + j;
    *(uint2*)&Xp[base]      = make_uint2(h0, h1);
    *(uint2*)&Xp[base + 32] = make_uint2(l0, l1);
}

// ================= bf16x3 GEMM, CTA 128x256, 512 threads, 64-k stages =======
// (EXACT R8 configuration — measured local optimum)
#define SUB_A 16384
#define SUB_B 32768
#define SUB_BYTES (SUB_A + SUB_B)        // 49152
#define STAGE_BYTES (2*SUB_BYTES)        // 98304
#define GEMM_SMEM (2*STAGE_BYTES + 256)  // NSTAGE=2
#define GTHREADS 512

__device__ __forceinline__ void gemm_k64(const __nv_bfloat16* __restrict__ Ap,
                                         const __nv_bfloat16* __restrict__ Bp,
                                         float* __restrict__ C,
                                         int N, int K, int bm, int bn, char* sm)
{
    const int tid  = threadIdx.x;          // 0..511
    const int lane = tid & 31;
    const int wid  = tid >> 5;             // 0..15
    const int wm = wid & 3;                // 4 m groups of 32 rows
    const int wn = wid >> 2;               // 4 n groups of 64 cols
    const uint32_t smb = (smem_u32(sm) + 127u) & ~127u;
    const int KT  = K >> 5;
    const int KT2 = K >> 6;

    const int r0  = tid >> 3;              // 0..63
    const int g16 = (tid & 7) * 16;
    uint32_t soffA[2], soffB[4];
#pragma unroll
    for (int q = 0; q < 2; ++q) soffA[q] = SWZ128((uint32_t)((r0 + q*64)*128 + g16));
#pragma unroll
    for (int q = 0; q < 4; ++q) soffB[q] = SWZ128((uint32_t)((r0 + q*64)*128 + g16));
    const char* Apb = (const char*)Ap + ((size_t)bm * 128) * (size_t)KT * 128;
    const char* Bpb = (const char*)Bp + ((size_t)bn * 256) * (size_t)KT * 128;

    const int lrow = ((lane >> 3) & 1) * 8 + (lane & 7);
    const int lkof = (lane >> 4) * 8;

    float acc[2][8][4];
#pragma unroll
    for (int i = 0; i < 2; ++i)
#pragma unroll
        for (int j = 0; j < 8; ++j)
#pragma unroll
            for (int r = 0; r < 4; ++r) acc[i][j][r] = 0.f;

    auto issue_stage = [&](int kt2, uint32_t sbase) {
#pragma unroll
        for (int sub = 0; sub < 2; ++sub) {
            const int kt = kt2*2 + sub;
            const uint32_t sa = sbase + sub * SUB_BYTES;
#pragma unroll
            for (int q = 0; q < 2; ++q)
                CP_ASYNC16(sa + soffA[q], Apb + ((size_t)(r0 + q*64) * KT + kt) * 128 + g16);
#pragma unroll
            for (int q = 0; q < 4; ++q)
                CP_ASYNC16(sa + SUB_A + soffB[q], Bpb + ((size_t)(r0 + q*64) * KT + kt) * 128 + g16);
        }
    };

    issue_stage(0, smb);
    CP_COMMIT();

    for (int kt2 = 0; kt2 < KT2; ++kt2) {
        CP_WAIT(0);
        __syncthreads();

        if (kt2 + 1 < KT2) issue_stage(kt2 + 1, smb + ((kt2 + 1) & 1) * STAGE_BYTES);
        CP_COMMIT();

        const uint32_t stg = smb + (kt2 & 1) * STAGE_BYTES;
#pragma unroll
        for (int sub = 0; sub < 2; ++sub) {
            const uint32_t sa = stg + sub * SUB_BYTES;
            const uint32_t sb = sa + SUB_A;
#pragma unroll
            for (int ks = 0; ks < 32; ks += 16) {
                uint32_t ah[2][4], al[2][4];
#pragma unroll
                for (int mt = 0; mt < 2; ++mt) {
                    uint32_t pre = (uint32_t)((wm*32 + mt*16 + lrow)*128 + (ks + lkof)*2);
                    uint32_t swz = SWZ128(pre);
                    LDMX4(ah[mt][0], ah[mt][1], ah[mt][2], ah[mt][3], sa + swz);
                    LDMX4(al[mt][0], al[mt][1], al[mt][2], al[mt][3], sa + (swz^64));
                }
                uint32_t bh[8][2], bl[8][2];
#pragma unroll
                for (int g = 0; g < 4; ++g) {
                    uint32_t pre = (uint32_t)((wn*64 + g*16 + lrow)*128 + (ks + lkof)*2);
                    uint32_t swz = SWZ128(pre);
                    uint32_t t0, t1, t2, t3;
                    LDMX4(t0, t1, t2, t3, sb + swz);
                    bh[2*g][0] = t0; bh[2*g][1] = t2;
                    bh[2*g+1][0] = t1; bh[2*g+1][1] = t3;
                    LDMX4(t0, t1, t2, t3, sb + (swz^64));
                    bl[2*g][0] = t0; bl[2*g][1] = t2;
                    bl[2*g+1][0] = t1; bl[2*g+1][1] = t3;
                }
                // term-major ordering: accumulator reuse separated by 15 MMAs
#pragma unroll
                for (int nt = 0; nt < 8; ++nt) {
                    MMA_BF16(acc[0][nt], ah[0], bh[nt]);
                    MMA_BF16(acc[1][nt], ah[1], bh[nt]);
                }
#pragma unroll
                for (int nt = 0; nt < 8; ++nt) {
                    MMA_BF16(acc[0][nt], ah[0], bl[nt]);
                    MMA_BF16(acc[1][nt], ah[1], bl[nt]);
                }
#pragma unroll
                for (int nt = 0; nt < 8; ++nt) {
                    MMA_BF16(acc[0][nt], al[0], bh[nt]);
                    MMA_BF16(acc[1][nt], al[1], bh[nt]);
                }
            }
        }
    }

    const int m0 = bm*128 + wm*32 + (lane >> 2);
    const int n0 = bn*256 + wn*64 + 2*(lane & 3);
#pragma unroll
    for (int mt = 0; mt < 2; ++mt)
#pragma unroll
        for (int nt = 0; nt < 8; ++nt) {
            float* c0 = C + (size_t)(m0 + mt*16) * N + n0 + nt*8;
            *(float2*)c0 = make_float2(acc[mt][nt][0], acc[mt][nt][1]);
            float* c1 = c0 + (size_t)8 * N;
            *(float2*)c1 = make_float2(acc[mt][nt][2], acc[mt][nt][3]);
        }
}

// merged qkv+z projection: bn 0..31 -> qkv, 32..47 -> z
__global__ void __launch_bounds__(GTHREADS, 1) gemm_qkvz(const __nv_bfloat16* __restrict__ xp,
                                                         const __nv_bfloat16* __restrict__ wqkvp,
                                                         const __nv_bfloat16* __restrict__ wzp,
                                                         float* __restrict__ qkv,
                                                         float* __restrict__ z)
{
    extern __shared__ char sm[];
    const int bn = blockIdx.x;
    if (bn < CONV_DIM/256)
        gemm_k64(xp, wqkvp, qkv, CONV_DIM, DIM, blockIdx.y, bn, sm);
    else
        gemm_k64(xp, wzp, z, VAL_DIM, DIM, blockIdx.y, bn - CONV_DIM/256, sm);
}

__global__ void __launch_bounds__(GTHREADS, 1) gemm_single(const __nv_bfloat16* __restrict__ Ap,
                                                           const __nv_bfloat16* __restrict__ Bp,
                                                           float* __restrict__ C,
                                                           int N, int K)
{
    extern __shared__ char sm[];
    gemm_k64(Ap, Bp, C, N, K, blockIdx.y, blockIdx.x, sm);
}

// ------------- small GEMM for a/b + fused g/beta epilogue -------------------
__global__ void __launch_bounds__(256) ab_gemm(const float* __restrict__ x,
                                               const float* __restrict__ Wa,
                                               const float* __restrict__ Wb,
                                               const float* __restrict__ A_log,
                                               const float* __restrict__ dt_bias,
                                               float* __restrict__ eg_out,
                                               float* __restrict__ beta_out)
{
    __shared__ float xs[16][65];
    __shared__ float ws[64][65];
    const int tid = threadIdx.x;
    const int m0  = blockIdx.x * 16;

    float acc[4] = {0.f, 0.f, 0.f, 0.f};
    const int r  = tid & 15;
    const int jg = tid >> 4;

    for (int k0 = 0; k0 < DIM; k0 += 64) {
        {
            int rr = tid >> 4;
            int cc = (tid & 15) * 4;
            float4 v = *(const float4*)&x[(size_t)(m0+rr)*DIM + k0 + cc];
            xs[rr][cc] = v.x; xs[rr][cc+1] = v.y; xs[rr][cc+2] = v.z; xs[rr][cc+3] = v.w;
        }
#pragma unroll
        for (int u = 0; u < 4; ++u) {
            int idx = tid + u*256;
            int j  = idx >> 4;
            int cc = (idx & 15) * 4;
            const float* W = (j < 32) ? &Wa[(size_t)j*DIM] : &Wb[(size_t)(j-32)*DIM];
            float4 v = *(const float4*)&W[k0 + cc];
            ws[j][cc] = v.x; ws[j][cc+1] = v.y; ws[j][cc+2] = v.z; ws[j][cc+3] = v.w;
        }
        __syncthreads();
#pragma unroll 8
        for (int k = 0; k < 64; ++k) {
            float xv = xs[r][k];
            acc[0] += xv * ws[jg*4+0][k];
            acc[1] += xv * ws[jg*4+1][k];
            acc[2] += xv * ws[jg*4+2][k];
            acc[3] += xv * ws[jg*4+3][k];
        }
        __syncthreads();
    }
    const int m = m0 + r;
#pragma unroll
    for (int u = 0; u < 4; ++u) {
        int j = jg*4 + u;
        float v = acc[u];
        if (j < 32) {
            float sp = v + dt_bias[j];
            sp = (sp > 20.f) ? sp : log1pf(expf(sp));
            eg_out[(size_t)m*HV + j] = expf(-expf(A_log[j]) * sp);
        } else {
            beta_out[(size_t)m*HV + (j-32)] = 1.f / (1.f + expf(-v));
        }
    }
}

// ------------- fused conv+SiLU+l2norm for q/k (warp = head x 64-step chunk) --
// grid: 2048 warps = 256 CTAs x 8 warps. lane covers 4 channels of the head.
__global__ void __launch_bounds__(256) convnorm_qk_kernel(const float* __restrict__ in,
                                                          float* __restrict__ out,
                                                          const float* __restrict__ w)
{
    const int gw   = blockIdx.x * 8 + (threadIdx.x >> 5);   // 0..2047
    const int lane = threadIdx.x & 31;
    const int chunk = gw & 31;            // 32 chunks of 64 steps
    const int h2    = (gw >> 5) & 31;     // 0..15 q heads, 16..31 k heads
    const int b     = gw >> 10;
    const int c     = h2*128 + lane*4;

    float4 wt[4];
#pragma unroll
    for (int i = 0; i < 4; ++i)
        wt[i] = *(const float4*)&w[(c + i)*4];

    const float* ip = in  + (size_t)b*LL*CONV_DIM + c;
    float*       op = out + (size_t)b*LL*CONV_DIM + c;
    const int l0 = chunk * 64;

    float4 xm3, xm2, xm1;
    if (l0 == 0) {
        xm3 = make_float4(0.f,0.f,0.f,0.f);
        xm2 = xm3; xm1 = xm3;
    } else {
        xm3 = *(const float4*)(ip + (size_t)(l0-3)*CONV_DIM);
        xm2 = *(const float4*)(ip + (size_t)(l0-2)*CONV_DIM);
        xm1 = *(const float4*)(ip + (size_t)(l0-1)*CONV_DIM);
    }
    const float qscale = (h2 < 16) ? 0.08838834764831845f : 1.f;

#pragma unroll 2
    for (int l = l0; l < l0 + 64; ++l) {
        float4 x0 = *(const float4*)(ip + (size_t)l*CONV_DIM);
        float h0 = xm3.x*wt[0].x + xm2.x*wt[0].y + xm1.x*wt[0].z + x0.x*wt[0].w;
        float h1 = xm3.y*wt[1].x + xm2.y*wt[1].y + xm1.y*wt[1].z + x0.y*wt[1].w;
        float h2v= xm3.z*wt[2].x + xm2.z*wt[2].y + xm1.z*wt[2].z + x0.z*wt[2].w;
        float h3 = xm3.w*wt[3].x + xm2.w*wt[3].y + xm1.w*wt[3].z + x0.w*wt[3].w;
        h0 = h0 / (1.f + expf(-h0));
        h1 = h1 / (1.f + expf(-h1));
        h2v= h2v/ (1.f + expf(-h2v));
        h3 = h3 / (1.f + expf(-h3));
        float ss = h0*h0 + h1*h1 + h2v*h2v + h3*h3;
#pragma unroll
        for (int o = 16; o; o >>= 1) ss += __shfl_xor_sync(0xffffffffu, ss, o);
        const float r = rsqrtf(ss + 1e-6f) * qscale;
        *(float4*)(op + (size_t)l*CONV_DIM) = make_float4(h0*r, h1*r, h2v*r, h3*r);
        xm3 = xm2; xm2 = xm1; xm1 = x0;
    }
}

// ------------- depthwise causal conv (K=4) + SiLU for v channels -------------
__global__ void __launch_bounds__(256) conv_v_kernel(const float* __restrict__ in,
                                                     float* __restrict__ out,
                                                     const float* __restrict__ w)
{
    const int c  = 2*KEY_DIM + blockIdx.x * 256 + threadIdx.x;
    const int lc = blockIdx.y;
    const int b  = blockIdx.z;
    const float w0 = w[c*4+0], w1 = w[c*4+1], w2 = w[c*4+2], w3 = w[c*4+3];
    const float* ip = in  + (size_t)b*LL*CONV_DIM + c;
    float*       op = out + (size_t)b*LL*CONV_DIM + c;
    const int l0 = lc * 128;
    float xm3, xm2, xm1;
    if (l0 == 0) { xm3 = xm2 = xm1 = 0.f; }
    else {
        xm3 = ip[(size_t)(l0-3)*CONV_DIM];
        xm2 = ip[(size_t)(l0-2)*CONV_DIM];
        xm1 = ip[(size_t)(l0-1)*CONV_DIM];
    }
#pragma unroll 4
    for (int l = l0; l < l0 + 128; ++l) {
        float x0 = ip[(size_t)l*CONV_DIM];
        float h = xm3*w0 + xm2*w1 + xm1*w2 + x0*w3;
        h = h / (1.f + expf(-h));
        op[(size_t)l*CONV_DIM] = h;
        xm3 = xm2; xm2 = xm1; xm1 = x0;
    }
}

// ------------- gated delta rule scan (EXACT R8 version) ----------------------
__global__ void __launch_bounds__(256, 1) scan_kernel(const float* __restrict__ qkv,
                                                      const float* __restrict__ eg,
                                                      const float* __restrict__ beta,
                                                      float* __restrict__ o)
{
    const int bi = blockIdx.x;
    const int vh = bi & 1;
    const int h  = (bi >> 1) & 31;
    const int b  = bi >> 6;
    const int hk = h >> 1;
    const int t  = threadIdx.x;
    const int kq   = t & 3;
    const int vloc = t >> 2;
    const int vcol = vh*64 + vloc;

    __shared__ float kq_s[2][256];
    __shared__ float egs[LL];
    __shared__ float bets[LL];

    for (int i = t; i < LL; i += 256) {
        egs[i]  = eg  [(size_t)(b*LL + i)*HV + h];
        bets[i] = beta[(size_t)(b*LL + i)*HV + h];
    }

    float s[32];
#pragma unroll
    for (int i = 0; i < 32; ++i) s[i] = 0.f;

    const float* base = qkv + (size_t)b*LL*CONV_DIM;
    const int kqoff = (t < 128) ? (KEY_DIM + hk*128 + t)
                                : (hk*128 + (t-128));
    const int voff  = 2*KEY_DIM + h*128 + vcol;
    float* optr = o + (size_t)b*LL*VAL_DIM + h*128 + vcol;

    kq_s[0][t] = base[kqoff];
    float vcur = base[voff];
    __syncthreads();

    int p = 0;
    for (int l = 0; l < LL; ++l) {
        float kqn = 0.f, vn = 0.f;
        if (l + 1 < LL) {
            kqn = base[(size_t)(l+1)*CONV_DIM + kqoff];
            vn  = base[(size_t)(l+1)*CONV_DIM + voff];
        }
        const float egv = egs[l];
        const float bv  = bets[l];
        const float* ks = &kq_s[p][kq*32];
        const float* qs = &kq_s[p][128 + kq*32];

        float kv0 = 0.f, kv1 = 0.f, kv2 = 0.f, kv3 = 0.f;
#pragma unroll
        for (int i = 0; i < 8; ++i) {
            kv0 += ks[i]    * s[i];
            kv1 += ks[i+8]  * s[i+8];
            kv2 += ks[i+16] * s[i+16];
            kv3 += ks[i+24] * s[i+24];
        }
        float kv = (kv0 + kv1) + (kv2 + kv3);
        kv += __shfl_xor_sync(0xffffffffu, kv, 1);
        kv += __shfl_xor_sync(0xffffffffu, kv, 2);
        kv *= egv;
        const float delta = (vcur - kv) * bv;

        float o0 = 0.f, o1 = 0.f, o2 = 0.f, o3 = 0.f;
#pragma unroll
        for (int i = 0; i < 8; ++i) {
            s[i]    = egv*s[i]    + ks[i]*delta;    o0 += qs[i]*s[i];
            s[i+8]  = egv*s[i+8]  + ks[i+8]*delta;  o1 += qs[i+8]*s[i+8];
            s[i+16] = egv*s[i+16] + ks[i+16]*delta; o2 += qs[i+16]*s[i+16];
            s[i+24] = egv*s[i+24] + ks[i+24]*delta; o3 += qs[i+24]*s[i+24];
        }
        float outv = (o0 + o1) + (o2 + o3);
        outv += __shfl_xor_sync(0xffffffffu, outv, 1);
        outv += __shfl_xor_sync(0xffffffffu, outv, 2);
        if (kq == 0) optr[(size_t)l*VAL_DIM] = outv;

        kq_s[p^1][t] = kqn;
        vcur = vn;
        __syncthreads();
        p ^= 1;
    }
}

// ------------- gated RMSNorm + pack to bf16 hi/lo ---------------------------
__global__ void __launch_bounds__(256) rmsgate_pack_kernel(const float* __restrict__ o,
                                                           const float* __restrict__ z,
                                                           const float* __restrict__ nw,
                                                           __nv_bfloat16* __restrict__ op)
{
    const int wid  = (blockIdx.x * blockDim.x + threadIdx.x) >> 5;
    const int lane = threadIdx.x & 31;
    const float* p  = o + (size_t)wid*128 + lane*4;
    const float* zp = z + (size_t)wid*128 + lane*4;
    float4 v = *(const float4*)p;
    float ss = v.x*v.x + v.y*v.y + v.z*v.z + v.w*v.w;
#pragma unroll
    for (int off = 16; off; off >>= 1) ss += __shfl_xor_sync(0xffffffffu, ss, off);
    const float r = rsqrtf(ss * (1.f/128.f) + 1e-6f);
    float4 zv = *(const float4*)zp;
    float4 w4 = *(const float4*)&nw[lane*4];
    float4 out;
    out.x = v.x * r * w4.x * (zv.x / (1.f + expf(-zv.x)));
    out.y = v.y * r * w4.y * (zv.y / (1.f + expf(-zv.y)));
    out.z = v.z * r * w4.z * (zv.z / (1.f + expf(-zv.z)));
    out.w = v.w * r * w4.w * (zv.w / (1.f + expf(-zv.w)));
    const int m = wid >> 5;
    const int h = wid & 31;
    const int c = h*128 + lane*4;
    const int kt = c >> 5, j = c & 31;
    uint32_t h0, l0, h1, l1;
    split_pair(out.x, out.y, h0, l0);
    split_pair(out.z, out.w, h1, l1);
    size_t base = ((size_t)m * (VAL_DIM >> 5) + kt) * 64 + j;
    *(uint2*)&op[base]      = make_uint2(h0, h1);
    *(uint2*)&op[base + 32] = make_uint2(l0, l1);
}

// ---------------- launch ----------------------------------------------------
extern "C" void kernel_launch(void* const* d_in, const int* in_sizes, int n_in,
                              void* d_out, int out_size)
{
    const float* x       = (const float*)d_in[0];
    const float* W_qkv   = (const float*)d_in[1];
    const float* W_z     = (const float*)d_in[2];
    const float* W_a     = (const float*)d_in[3];
    const float* W_b     = (const float*)d_in[4];
    const float* conv_w  = (const float*)d_in[5];
    const float* A_log   = (const float*)d_in[6];
    const float* dt_bias = (const float*)d_in[7];
    const float* norm_w  = (const float*)d_in[8];
    const float* W_out   = (const float*)d_in[9];
    float* out = (float*)d_out;

    float *qkv, *cnv, *z, *eg, *bet, *o;
    __nv_bfloat16 *xp, *wqkvp, *wzp, *woutp, *op;
    cudaGetSymbolAddress((void**)&qkv, g_qkv);
    cudaGetSymbolAddress((void**)&cnv, g_conv);
    cudaGetSymbolAddress((void**)&z,   g_z);
    cudaGetSymbolAddress((void**)&eg,  g_eg);
    cudaGetSymbolAddress((void**)&bet, g_beta);
    cudaGetSymbolAddress((void**)&o,   g_o);
    cudaGetSymbolAddress((void**)&xp,    g_xp);
    cudaGetSymbolAddress((void**)&wqkvp, g_wqkvp);
    cudaGetSymbolAddress((void**)&wzp,   g_wzp);
    cudaGetSymbolAddress((void**)&woutp, g_woutp);
    cudaGetSymbolAddress((void**)&op,    g_op);

    cudaFuncSetAttribute(gemm_qkvz,   cudaFuncAttributeMaxDynamicSharedMemorySize, GEMM_SMEM);
    cudaFuncSetAttribute(gemm_single, cudaFuncAttributeMaxDynamicSharedMemorySize, GEMM_SMEM);

    // 0) packs — merged GEMM is the 4th launch (ncu capture)
    pack_kernel<<<(MTOT*DIM/4)/256, 256>>>(x, xp, DIM);
    pack_kernel<<<((size_t)CONV_DIM*DIM/4)/256, 256>>>(W_qkv, wqkvp, DIM);
    pack_kernel<<<((size_t)VAL_DIM*DIM/4)/256, 256>>>(W_z, wzp, DIM);
    // 1) merged qkv + z projection
    gemm_qkvz<<<dim3(CONV_DIM/256 + VAL_DIM/256, MTOT/128), GTHREADS, GEMM_SMEM>>>(
        xp, wqkvp, wzp, qkv, z);
    // 2) remaining pack + a/b
    pack_kernel<<<((size_t)DIM*VAL_DIM/4)/256, 256>>>(W_out, woutp, VAL_DIM);
    ab_gemm<<<MTOT/16, 256>>>(x, W_a, W_b, A_log, dt_bias, eg, bet);
    // 3) fused conv+silu+l2norm (q/k, 256 CTAs) and conv+silu (v)
    convnorm_qk_kernel<<<256, 256>>>(qkv, cnv, conv_w);
    conv_v_kernel<<<dim3(VAL_DIM/256, LL/128, BB), 256>>>(qkv, cnv, conv_w);
    // 4) scan
    scan_kernel<<<BB*HV*2, 256>>>(cnv, eg, bet, o);
    // 5) gated RMSNorm + pack
    rmsgate_pack_kernel<<<(BB*LL*HV)/8, 256>>>(o, z, norm_w, op);
    // 6) output projection
    gemm_single<<<dim3(DIM/256, MTOT/128), GTHREADS, GEMM_SMEM>>>(op, woutp, out, DIM, VAL_DIM);
}

// round 15
// speedup vs baseline: 1.0470x; 1.0078x over previous
#include <cuda_runtime.h>
#include <cuda_bf16.h>
#include <math.h>
#include <cstdint>

// ---------------- problem constants ----------------
#define BB 2
#define LL 2048
#define DIM 2048
#define HK 16
#define HV 32
#define DK 128
#define DV 128
#define KCONV 4
#define KEY_DIM (HK*DK)            // 2048
#define VAL_DIM (HV*DV)            // 4096
#define CONV_DIM (2*KEY_DIM+VAL_DIM) // 8192
#define MTOT (BB*LL)               // 4096

// ---------------- scratch ----------------
__device__ float g_qkv [ (size_t)BB*LL*CONV_DIM ];
__device__ float g_conv[ (size_t)BB*LL*CONV_DIM ];
__device__ float g_z   [ (size_t)BB*LL*VAL_DIM  ];
__device__ float g_eg  [ (size_t)BB*LL*HV ];
__device__ float g_beta[ (size_t)BB*LL*HV ];
__device__ float g_o   [ (size_t)BB*LL*VAL_DIM  ];
__device__ __nv_bfloat16 g_xp   [ (size_t)MTOT*DIM*2 ];
__device__ __nv_bfloat16 g_wqkvp[ (size_t)CONV_DIM*DIM*2 ];
__device__ __nv_bfloat16 g_wzp  [ (size_t)VAL_DIM*DIM*2 ];
__device__ __nv_bfloat16 g_woutp[ (size_t)DIM*VAL_DIM*2 ];
__device__ __nv_bfloat16 g_op   [ (size_t)MTOT*VAL_DIM*2 ];

// ================= helpers ==================================================
__device__ __forceinline__ uint32_t smem_u32(const void* p) {
    uint32_t a;
    asm("{ .reg .u64 t; cvta.to.shared.u64 t, %1; cvt.u32.u64 %0, t; }"
        : "=r"(a) : "l"(p));
    return a;
}
#define SWZ128(off) ((off) ^ (((off) >> 3) & 0x70))

#define LDMX4(r0, r1, r2, r3, addr) \
    asm volatile("ldmatrix.sync.aligned.m8n8.x4.shared.b16 {%0,%1,%2,%3}, [%4];" \
        : "=r"(r0), "=r"(r1), "=r"(r2), "=r"(r3) : "r"(addr))

#define MMA_BF16(d, a, b) \
    asm volatile("mma.sync.aligned.m16n8k16.row.col.f32.bf16.bf16.f32 " \
        "{%0,%1,%2,%3}, {%4,%5,%6,%7}, {%8,%9}, {%0,%1,%2,%3};" \
        : "+f"((d)[0]), "+f"((d)[1]), "+f"((d)[2]), "+f"((d)[3]) \
        : "r"((a)[0]), "r"((a)[1]), "r"((a)[2]), "r"((a)[3]), \
          "r"((b)[0]), "r"((b)[1]))

#define CP_ASYNC16(smem, gmem) \
    asm volatile("cp.async.cg.shared.global [%0], [%1], 16;" \
                 :: "r"(smem), "l"(gmem) : "memory")
#define CP_COMMIT() asm volatile("cp.async.commit_group;" ::: "memory")
#define CP_WAIT(n)  asm volatile("cp.async.wait_group %0;" :: "n"(n) : "memory")

__device__ __forceinline__ void split_pair(float x, float y,
                                           uint32_t& hi, uint32_t& lo) {
    __nv_bfloat16 hx = __float2bfloat16(x);
    __nv_bfloat16 hy = __float2bfloat16(y);
    __nv_bfloat162 h(hx, hy);
    hi = *reinterpret_cast<uint32_t*>(&h);
    __nv_bfloat162 l(__float2bfloat16(x - __bfloat162float(hx)),
                     __float2bfloat16(y - __bfloat162float(hy)));
    lo = *reinterpret_cast<uint32_t*>(&l);
}

// ------------- pack: fp32 [R][K] -> bf16 hi/lo rows of 128B ------------------
__global__ void __launch_bounds__(256) pack_kernel(const float* __restrict__ X,
                                                   __nv_bfloat16* __restrict__ Xp,
                                                   int K)
{
    const int idx = blockIdx.x * 256 + threadIdx.x;
    const int kq  = K >> 2;
    const int r   = idx / kq;
    const int k0  = (idx - r * kq) * 4;
    const int kt  = k0 >> 5;
    const int j   = k0 & 31;
    float4 v = *(const float4*)&X[(size_t)r * K + k0];
    uint32_t h0, l0, h1, l1;
    split_pair(v.x, v.y, h0, l0);
    split_pair(v.z, v.w, h1, l1);
    size_t base = ((size_t)r * (K >> 5) + kt) * 64 + j;
    *(uint2*)&Xp[base]      = make_uint2(h0, h1);
    *(uint2*)&Xp[base + 32] = make_uint2(l0, l1);
}

// ================= bf16x3 GEMM, CTA 128x256, 512 threads, 64-k stages =======
// (EXACT R8 configuration — measured local optimum)
#define SUB_A 16384
#define SUB_B 32768
#define SUB_BYTES (SUB_A + SUB_B)        // 49152
#define STAGE_BYTES (2*SUB_BYTES)        // 98304
#define GEMM_SMEM (2*STAGE_BYTES + 256)  // NSTAGE=2
#define GTHREADS 512

__device__ __forceinline__ void gemm_k64(const __nv_bfloat16* __restrict__ Ap,
                                         const __nv_bfloat16* __restrict__ Bp,
                                         float* __restrict__ C,
                                         int N, int K, int bm, int bn, char* sm)
{
    const int tid  = threadIdx.x;          // 0..511
    const int lane = tid & 31;
    const int wid  = tid >> 5;             // 0..15
    const int wm = wid & 3;                // 4 m groups of 32 rows
    const int wn = wid >> 2;               // 4 n groups of 64 cols
    const uint32_t smb = (smem_u32(sm) + 127u) & ~127u;
    const int KT  = K >> 5;
    const int KT2 = K >> 6;

    const int r0  = tid >> 3;              // 0..63
    const int g16 = (tid & 7) * 16;
    uint32_t soffA[2], soffB[4];
#pragma unroll
    for (int q = 0; q < 2; ++q) soffA[q] = SWZ128((uint32_t)((r0 + q*64)*128 + g16));
#pragma unroll
    for (int q = 0; q < 4; ++q) soffB[q] = SWZ128((uint32_t)((r0 + q*64)*128 + g16));
    const char* Apb = (const char*)Ap + ((size_t)bm * 128) * (size_t)KT * 128;
    const char* Bpb = (const char*)Bp + ((size_t)bn * 256) * (size_t)KT * 128;

    const int lrow = ((lane >> 3) & 1) * 8 + (lane & 7);
    const int lkof = (lane >> 4) * 8;

    float acc[2][8][4];
#pragma unroll
    for (int i = 0; i < 2; ++i)
#pragma unroll
        for (int j = 0; j < 8; ++j)
#pragma unroll
            for (int r = 0; r < 4; ++r) acc[i][j][r] = 0.f;

    auto issue_stage = [&](int kt2, uint32_t sbase) {
#pragma unroll
        for (int sub = 0; sub < 2; ++sub) {
            const int kt = kt2*2 + sub;
            const uint32_t sa = sbase + sub * SUB_BYTES;
#pragma unroll
            for (int q = 0; q < 2; ++q)
                CP_ASYNC16(sa + soffA[q], Apb + ((size_t)(r0 + q*64) * KT + kt) * 128 + g16);
#pragma unroll
            for (int q = 0; q < 4; ++q)
                CP_ASYNC16(sa + SUB_A + soffB[q], Bpb + ((size_t)(r0 + q*64) * KT + kt) * 128 + g16);
        }
    };

    issue_stage(0, smb);
    CP_COMMIT();

    for (int kt2 = 0; kt2 < KT2; ++kt2) {
        CP_WAIT(0);
        __syncthreads();

        if (kt2 + 1 < KT2) issue_stage(kt2 + 1, smb + ((kt2 + 1) & 1) * STAGE_BYTES);
        CP_COMMIT();

        const uint32_t stg = smb + (kt2 & 1) * STAGE_BYTES;
#pragma unroll
        for (int sub = 0; sub < 2; ++sub) {
            const uint32_t sa = stg + sub * SUB_BYTES;
            const uint32_t sb = sa + SUB_A;
#pragma unroll
            for (int ks = 0; ks < 32; ks += 16) {
                uint32_t ah[2][4], al[2][4];
#pragma unroll
                for (int mt = 0; mt < 2; ++mt) {
                    uint32_t pre = (uint32_t)((wm*32 + mt*16 + lrow)*128 + (ks + lkof)*2);
                    uint32_t swz = SWZ128(pre);
                    LDMX4(ah[mt][0], ah[mt][1], ah[mt][2], ah[mt][3], sa + swz);
                    LDMX4(al[mt][0], al[mt][1], al[mt][2], al[mt][3], sa + (swz^64));
                }
                uint32_t bh[8][2], bl[8][2];
#pragma unroll
                for (int g = 0; g < 4; ++g) {
                    uint32_t pre = (uint32_t)((wn*64 + g*16 + lrow)*128 + (ks + lkof)*2);
                    uint32_t swz = SWZ128(pre);
                    uint32_t t0, t1, t2, t3;
                    LDMX4(t0, t1, t2, t3, sb + swz);
                    bh[2*g][0] = t0; bh[2*g][1] = t2;
                    bh[2*g+1][0] = t1; bh[2*g+1][1] = t3;
                    LDMX4(t0, t1, t2, t3, sb + (swz^64));
                    bl[2*g][0] = t0; bl[2*g][1] = t2;
                    bl[2*g+1][0] = t1; bl[2*g+1][1] = t3;
                }
                // term-major ordering: accumulator reuse separated by 15 MMAs
#pragma unroll
                for (int nt = 0; nt < 8; ++nt) {
                    MMA_BF16(acc[0][nt], ah[0], bh[nt]);
                    MMA_BF16(acc[1][nt], ah[1], bh[nt]);
                }
#pragma unroll
                for (int nt = 0; nt < 8; ++nt) {
                    MMA_BF16(acc[0][nt], ah[0], bl[nt]);
                    MMA_BF16(acc[1][nt], ah[1], bl[nt]);
                }
#pragma unroll
                for (int nt = 0; nt < 8; ++nt) {
                    MMA_BF16(acc[0][nt], al[0], bh[nt]);
                    MMA_BF16(acc[1][nt], al[1], bh[nt]);
                }
            }
        }
    }

    const int m0 = bm*128 + wm*32 + (lane >> 2);
    const int n0 = bn*256 + wn*64 + 2*(lane & 3);
#pragma unroll
    for (int mt = 0; mt < 2; ++mt)
#pragma unroll
        for (int nt = 0; nt < 8; ++nt) {
            float* c0 = C + (size_t)(m0 + mt*16) * N + n0 + nt*8;
            *(float2*)c0 = make_float2(acc[mt][nt][0], acc[mt][nt][1]);
            float* c1 = c0 + (size_t)8 * N;
            *(float2*)c1 = make_float2(acc[mt][nt][2], acc[mt][nt][3]);
        }
}

// merged qkv+z projection: bn 0..31 -> qkv, 32..47 -> z
__global__ void __launch_bounds__(GTHREADS, 1) gemm_qkvz(const __nv_bfloat16* __restrict__ xp,
                                                         const __nv_bfloat16* __restrict__ wqkvp,
                                                         const __nv_bfloat16* __restrict__ wzp,
                                                         float* __restrict__ qkv,
                                                         float* __restrict__ z)
{
    extern __shared__ char sm[];
    const int bn = blockIdx.x;
    if (bn < CONV_DIM/256)
        gemm_k64(xp, wqkvp, qkv, CONV_DIM, DIM, blockIdx.y, bn, sm);
    else
        gemm_k64(xp, wzp, z, VAL_DIM, DIM, blockIdx.y, bn - CONV_DIM/256, sm);
}

__global__ void __launch_bounds__(GTHREADS, 1) gemm_single(const __nv_bfloat16* __restrict__ Ap,
                                                           const __nv_bfloat16* __restrict__ Bp,
                                                           float* __restrict__ C,
                                                           int N, int K)
{
    extern __shared__ char sm[];
    gemm_k64(Ap, Bp, C, N, K, blockIdx.y, blockIdx.x, sm);
}

// ------------- small GEMM for a/b + fused g/beta epilogue -------------------
__global__ void __launch_bounds__(256) ab_gemm(const float* __restrict__ x,
                                               const float* __restrict__ Wa,
                                               const float* __restrict__ Wb,
                                               const float* __restrict__ A_log,
                                               const float* __restrict__ dt_bias,
                                               float* __restrict__ eg_out,
                                               float* __restrict__ beta_out)
{
    __shared__ float xs[16][65];
    __shared__ float ws[64][65];
    const int tid = threadIdx.x;
    const int m0  = blockIdx.x * 16;

    float acc[4] = {0.f, 0.f, 0.f, 0.f};
    const int r  = tid & 15;
    const int jg = tid >> 4;

    for (int k0 = 0; k0 < DIM; k0 += 64) {
        {
            int rr = tid >> 4;
            int cc = (tid & 15) * 4;
            float4 v = *(const float4*)&x[(size_t)(m0+rr)*DIM + k0 + cc];
            xs[rr][cc] = v.x; xs[rr][cc+1] = v.y; xs[rr][cc+2] = v.z; xs[rr][cc+3] = v.w;
        }
#pragma unroll
        for (int u = 0; u < 4; ++u) {
            int idx = tid + u*256;
            int j  = idx >> 4;
            int cc = (idx & 15) * 4;
            const float* W = (j < 32) ? &Wa[(size_t)j*DIM] : &Wb[(size_t)(j-32)*DIM];
            float4 v = *(const float4*)&W[k0 + cc];
            ws[j][cc] = v.x; ws[j][cc+1] = v.y; ws[j][cc+2] = v.z; ws[j][cc+3] = v.w;
        }
        __syncthreads();
#pragma unroll 8
        for (int k = 0; k < 64; ++k) {
            float xv = xs[r][k];
            acc[0] += xv * ws[jg*4+0][k];
            acc[1] += xv * ws[jg*4+1][k];
            acc[2] += xv * ws[jg*4+2][k];
            acc[3] += xv * ws[jg*4+3][k];
        }
        __syncthreads();
    }
    const int m = m0 + r;
#pragma unroll
    for (int u = 0; u < 4; ++u) {
        int j = jg*4 + u;
        float v = acc[u];
        if (j < 32) {
            float sp = v + dt_bias[j];
            sp = (sp > 20.f) ? sp : log1pf(expf(sp));
            eg_out[(size_t)m*HV + j] = expf(-expf(A_log[j]) * sp);
        } else {
            beta_out[(size_t)m*HV + (j-32)] = 1.f / (1.f + expf(-v));
        }
    }
}

// ------------- depthwise causal conv (K=4) + SiLU ---------------------------
__global__ void __launch_bounds__(256) conv_silu_kernel(const float* __restrict__ in,
                                                        float* __restrict__ out,
                                                        const float* __restrict__ w)
{
    const int c  = blockIdx.x * 256 + threadIdx.x;
    const int lc = blockIdx.y;
    const int b  = blockIdx.z;
    const float w0 = w[c*4+0], w1 = w[c*4+1], w2 = w[c*4+2], w3 = w[c*4+3];
    const float* ip = in  + (size_t)b*LL*CONV_DIM + c;
    float*       op = out + (size_t)b*LL*CONV_DIM + c;
    const int l0 = lc * 128;
    float xm3, xm2, xm1;
    if (l0 == 0) { xm3 = xm2 = xm1 = 0.f; }
    else {
        xm3 = ip[(size_t)(l0-3)*CONV_DIM];
        xm2 = ip[(size_t)(l0-2)*CONV_DIM];
        xm1 = ip[(size_t)(l0-1)*CONV_DIM];
    }
#pragma unroll 4
    for (int l = l0; l < l0 + 128; ++l) {
        float x0 = ip[(size_t)l*CONV_DIM];
        float h = xm3*w0 + xm2*w1 + xm1*w2 + x0*w3;
        h = h / (1.f + expf(-h));
        op[(size_t)l*CONV_DIM] = h;
        xm3 = xm2; xm2 = xm1; xm1 = x0;
    }
}

// ------------- l2norm of q and k heads (in place) ---------------------------
__global__ void __launch_bounds__(256) qknorm_kernel(float* __restrict__ d)
{
    const int wid  = (blockIdx.x * blockDim.x + threadIdx.x) >> 5;
    const int lane = threadIdx.x & 31;
    const int h2 = wid & 31;
    const int l  = (wid >> 5) & (LL-1);
    const int b  = wid >> 16;
    float* p = d + ((size_t)(b*LL + l))*CONV_DIM + h2*128 + lane*4;
    float4 v = *(float4*)p;
    float ss = v.x*v.x + v.y*v.y + v.z*v.z + v.w*v.w;
#pragma unroll
    for (int o = 16; o; o >>= 1) ss += __shfl_xor_sync(0xffffffffu, ss, o);
    float r = rsqrtf(ss + 1e-6f);
    if (h2 < 16) r *= 0.08838834764831845f;
    v.x *= r; v.y *= r; v.z *= r; v.w *= r;
    *(float4*)p = v;
}

// ------------- gated delta rule scan ----------------------------------------
__global__ void __launch_bounds__(256, 1) scan_kernel(const float* __restrict__ qkv,
                                                      const float* __restrict__ eg,
                                                      const float* __restrict__ beta,
                                                      float* __restrict__ o)
{
    const int bi = blockIdx.x;
    const int vh = bi & 1;
    const int h  = (bi >> 1) & 31;
    const int b  = bi >> 6;
    const int hk = h >> 1;
    const int t  = threadIdx.x;
    const int kq   = t & 3;
    const int vloc = t >> 2;
    const int vcol = vh*64 + vloc;

    __shared__ float kq_s[2][256];
    __shared__ float egs[LL];
    __shared__ float bets[LL];

    for (int i = t; i < LL; i += 256) {
        egs[i]  = eg  [(size_t)(b*LL + i)*HV + h];
        bets[i] = beta[(size_t)(b*LL + i)*HV + h];
    }

    float s[32];
#pragma unroll
    for (int i = 0; i < 32; ++i) s[i] = 0.f;

    const float* base = qkv + (size_t)b*LL*CONV_DIM;
    const int kqoff = (t < 128) ? (KEY_DIM + hk*128 + t)
                                : (hk*128 + (t-128));
    const int voff  = 2*KEY_DIM + h*128 + vcol;
    float* optr = o + (size_t)b*LL*VAL_DIM + h*128 + vcol;

    kq_s[0][t] = base[kqoff];
    float vcur = base[voff];
    __syncthreads();

    int p = 0;
    for (int l = 0; l < LL; ++l) {
        float kqn = 0.f, vn = 0.f;
        if (l + 1 < LL) {
            kqn = base[(size_t)(l+1)*CONV_DIM + kqoff];
            vn  = base[(size_t)(l+1)*CONV_DIM + voff];
        }
        const float egv = egs[l];
        const float bv  = bets[l];
        const float* ks = &kq_s[p][kq*32];
        const float* qs = &kq_s[p][128 + kq*32];

        float kv0 = 0.f, kv1 = 0.f, kv2 = 0.f, kv3 = 0.f;
#pragma unroll
        for (int i = 0; i < 8; ++i) {
            kv0 += ks[i]    * s[i];
            kv1 += ks[i+8]  * s[i+8];
            kv2 += ks[i+16] * s[i+16];
            kv3 += ks[i+24] * s[i+24];
        }
        float kv = (kv0 + kv1) + (kv2 + kv3);
        kv += __shfl_xor_sync(0xffffffffu, kv, 1);
        kv += __shfl_xor_sync(0xffffffffu, kv, 2);
        kv *= egv;
        const float delta = (vcur - kv) * bv;

        float o0 = 0.f, o1 = 0.f, o2 = 0.f, o3 = 0.f;
#pragma unroll
        for (int i = 0; i < 8; ++i) {
            s[i]    = egv*s[i]    + ks[i]*delta;    o0 += qs[i]*s[i];
            s[i+8]  = egv*s[i+8]  + ks[i+8]*delta;  o1 += qs[i+8]*s[i+8];
            s[i+16] = egv*s[i+16] + ks[i+16]*delta; o2 += qs[i+16]*s[i+16];
            s[i+24] = egv*s[i+24] + ks[i+24]*delta; o3 += qs[i+24]*s[i+24];
        }
        float outv = (o0 + o1) + (o2 + o3);
        outv += __shfl_xor_sync(0xffffffffu, outv, 1);
        outv += __shfl_xor_sync(0xffffffffu, outv, 2);
        if (kq == 0) optr[(size_t)l*VAL_DIM] = outv;

        kq_s[p^1][t] = kqn;
        vcur = vn;
        __syncthreads();
        p ^= 1;
    }
}

// ------------- gated RMSNorm + pack to bf16 hi/lo ---------------------------
__global__ void __launch_bounds__(256) rmsgate_pack_kernel(const float* __restrict__ o,
                                                           const float* __restrict__ z,
                                                           const float* __restrict__ nw,
                                                           __nv_bfloat16* __restrict__ op)
{
    const int wid  = (blockIdx.x * blockDim.x + threadIdx.x) >> 5;
    const int lane = threadIdx.x & 31;
    const float* p  = o + (size_t)wid*128 + lane*4;
    const float* zp = z + (size_t)wid*128 + lane*4;
    float4 v = *(const float4*)p;
    float ss = v.x*v.x + v.y*v.y + v.z*v.z + v.w*v.w;
#pragma unroll
    for (int off = 16; off; off >>= 1) ss += __shfl_xor_sync(0xffffffffu, ss, off);
    const float r = rsqrtf(ss * (1.f/128.f) + 1e-6f);
    float4 zv = *(const float4*)zp;
    float4 w4 = *(const float4*)&nw[lane*4];
    float4 out;
    out.x = v.x * r * w4.x * (zv.x / (1.f + expf(-zv.x)));
    out.y = v.y * r * w4.y * (zv.y / (1.f + expf(-zv.y)));
    out.z = v.z * r * w4.z * (zv.z / (1.f + expf(-zv.z)));
    out.w = v.w * r * w4.w * (zv.w / (1.f + expf(-zv.w)));
    const int m = wid >> 5;
    const int h = wid & 31;
    const int c = h*128 + lane*4;
    const int kt = c >> 5, j = c & 31;
    uint32_t h0, l0, h1, l1;
    split_pair(out.x, out.y, h0, l0);
    split_pair(out.z, out.w, h1, l1);
    size_t base = ((size_t)m * (VAL_DIM >> 5) + kt) * 64 + j;
    *(uint2*)&op[base]      = make_uint2(h0, h1);
    *(uint2*)&op[base + 32] = make_uint2(l0, l1);
}

// ---------------- launch ----------------------------------------------------
extern "C" void kernel_launch(void* const* d_in, const int* in_sizes, int n_in,
                              void* d_out, int out_size)
{
    const float* x       = (const float*)d_in[0];
    const float* W_qkv   = (const float*)d_in[1];
    const float* W_z     = (const float*)d_in[2];
    const float* W_a     = (const float*)d_in[3];
    const float* W_b     = (const float*)d_in[4];
    const float* conv_w  = (const float*)d_in[5];
    const float* A_log   = (const float*)d_in[6];
    const float* dt_bias = (const float*)d_in[7];
    const float* norm_w  = (const float*)d_in[8];
    const float* W_out   = (const float*)d_in[9];
    float* out = (float*)d_out;

    float *qkv, *cnv, *z, *eg, *bet, *o;
    __nv_bfloat16 *xp, *wqkvp, *wzp, *woutp, *op;
    cudaGetSymbolAddress((void**)&qkv, g_qkv);
    cudaGetSymbolAddress((void**)&cnv, g_conv);
    cudaGetSymbolAddress((void**)&z,   g_z);
    cudaGetSymbolAddress((void**)&eg,  g_eg);
    cudaGetSymbolAddress((void**)&bet, g_beta);
    cudaGetSymbolAddress((void**)&o,   g_o);
    cudaGetSymbolAddress((void**)&xp,    g_xp);
    cudaGetSymbolAddress((void**)&wqkvp, g_wqkvp);
    cudaGetSymbolAddress((void**)&wzp,   g_wzp);
    cudaGetSymbolAddress((void**)&woutp, g_woutp);
    cudaGetSymbolAddress((void**)&op,    g_op);

    cudaFuncSetAttribute(gemm_qkvz,   cudaFuncAttributeMaxDynamicSharedMemorySize, GEMM_SMEM);
    cudaFuncSetAttribute(gemm_single, cudaFuncAttributeMaxDynamicSharedMemorySize, GEMM_SMEM);

    // 0) packs — merged GEMM is the 4th launch (ncu capture)
    pack_kernel<<<(MTOT*DIM/4)/256, 256>>>(x, xp, DIM);
    pack_kernel<<<((size_t)CONV_DIM*DIM/4)/256, 256>>>(W_qkv, wqkvp, DIM);
    pack_kernel<<<((size_t)VAL_DIM*DIM/4)/256, 256>>>(W_z, wzp, DIM);
    // 1) merged qkv + z projection
    gemm_qkvz<<<dim3(CONV_DIM/256 + VAL_DIM/256, MTOT/128), GTHREADS, GEMM_SMEM>>>(
        xp, wqkvp, wzp, qkv, z);
    // 2) remaining pack + a/b
    pack_kernel<<<((size_t)DIM*VAL_DIM/4)/256, 256>>>(W_out, woutp, VAL_DIM);
    ab_gemm<<<MTOT/16, 256>>>(x, W_a, W_b, A_log, dt_bias, eg, bet);
    // 3) conv + qknorm
    conv_silu_kernel<<<dim3(CONV_DIM/256, LL/128, BB), 256>>>(qkv, cnv, conv_w);
    qknorm_kernel<<<(BB*LL*32)/8, 256>>>(cnv);
    // 4) scan
    scan_kernel<<<BB*HV*2, 256>>>(cnv, eg, bet, o);
    // 5) gated RMSNorm + pack
    rmsgate_pack_kernel<<<(BB*LL*HV)/8, 256>>>(o, z, norm_w, op);
    // 6) output projection
    gemm_single<<<dim3(DIM/256, MTOT/128), GTHREADS, GEMM_SMEM>>>(op, woutp, out, DIM, VAL_DIM);
}

// round 16
// speedup vs baseline: 1.4911x; 1.4242x over previous
#include <cuda_runtime.h>
#include <cuda_bf16.h>
#include <math.h>
#include <cstdint>

// ---------------- problem constants ----------------
#define BB 2
#define LL 2048
#define DIM 2048
#define HK 16
#define HV 32
#define DK 128
#define DV 128
#define KCONV 4
#define KEY_DIM (HK*DK)            // 2048
#define VAL_DIM (HV*DV)            // 4096
#define CONV_DIM (2*KEY_DIM+VAL_DIM) // 8192
#define MTOT (BB*LL)               // 4096

// ---------------- scratch ----------------
__device__ float g_qkv [ (size_t)BB*LL*CONV_DIM ];
__device__ float g_conv[ (size_t)BB*LL*CONV_DIM ];
__device__ float g_z   [ (size_t)BB*LL*VAL_DIM  ];
__device__ float g_eg  [ (size_t)BB*LL*HV ];
__device__ float g_beta[ (size_t)BB*LL*HV ];
__device__ float g_o   [ (size_t)BB*LL*VAL_DIM  ];
__device__ __nv_bfloat16 g_xp   [ (size_t)MTOT*DIM*2 ];
__device__ __nv_bfloat16 g_wqkvp[ (size_t)CONV_DIM*DIM*2 ];
__device__ __nv_bfloat16 g_wzp  [ (size_t)VAL_DIM*DIM*2 ];
__device__ __nv_bfloat16 g_woutp[ (size_t)DIM*VAL_DIM*2 ];
__device__ __nv_bfloat16 g_op   [ (size_t)MTOT*VAL_DIM*2 ];

// ================= helpers ==================================================
__device__ __forceinline__ uint32_t smem_u32(const void* p) {
    uint32_t a;
    asm("{ .reg .u64 t; cvta.to.shared.u64 t, %1; cvt.u32.u64 %0, t; }"
        : "=r"(a) : "l"(p));
    return a;
}
#define SWZ128(off) ((off) ^ (((off) >> 3) & 0x70))

#define LDMX4(r0, r1, r2, r3, addr) \
    asm volatile("ldmatrix.sync.aligned.m8n8.x4.shared.b16 {%0,%1,%2,%3}, [%4];" \
        : "=r"(r0), "=r"(r1), "=r"(r2), "=r"(r3) : "r"(addr))

#define MMA_BF16(d, a, b) \
    asm volatile("mma.sync.aligned.m16n8k16.row.col.f32.bf16.bf16.f32 " \
        "{%0,%1,%2,%3}, {%4,%5,%6,%7}, {%8,%9}, {%0,%1,%2,%3};" \
        : "+f"((d)[0]), "+f"((d)[1]), "+f"((d)[2]), "+f"((d)[3]) \
        : "r"((a)[0]), "r"((a)[1]), "r"((a)[2]), "r"((a)[3]), \
          "r"((b)[0]), "r"((b)[1]))

#define CP_ASYNC16(smem, gmem) \
    asm volatile("cp.async.cg.shared.global [%0], [%1], 16;" \
                 :: "r"(smem), "l"(gmem) : "memory")
#define CP_ASYNC4(smem, gmem) \
    asm volatile("cp.async.ca.shared.global [%0], [%1], 4;" \
                 :: "r"(smem), "l"(gmem) : "memory")
#define CP_COMMIT() asm volatile("cp.async.commit_group;" ::: "memory")
#define CP_WAIT(n)  asm volatile("cp.async.wait_group %0;" :: "n"(n) : "memory")

__device__ __forceinline__ void split_pair(float x, float y,
                                           uint32_t& hi, uint32_t& lo) {
    __nv_bfloat16 hx = __float2bfloat16(x);
    __nv_bfloat16 hy = __float2bfloat16(y);
    __nv_bfloat162 h(hx, hy);
    hi = *reinterpret_cast<uint32_t*>(&h);
    __nv_bfloat162 l(__float2bfloat16(x - __bfloat162float(hx)),
                     __float2bfloat16(y - __bfloat162float(hy)));
    lo = *reinterpret_cast<uint32_t*>(&l);
}

// ------------- pack: fp32 [R][K] -> bf16 hi/lo rows of 128B ------------------
__global__ void __launch_bounds__(256) pack_kernel(const float* __restrict__ X,
                                                   __nv_bfloat16* __restrict__ Xp,
                                                   int K)
{
    const int idx = blockIdx.x * 256 + threadIdx.x;
    const int kq  = K >> 2;
    const int r   = idx / kq;
    const int k0  = (idx - r * kq) * 4;
    const int kt  = k0 >> 5;
    const int j   = k0 & 31;
    float4 v = *(const float4*)&X[(size_t)r * K + k0];
    uint32_t h0, l0, h1, l1;
    split_pair(v.x, v.y, h0, l0);
    split_pair(v.z, v.w, h1, l1);
    size_t base = ((size_t)r * (K >> 5) + kt) * 64 + j;
    *(uint2*)&Xp[base]      = make_uint2(h0, h1);
    *(uint2*)&Xp[base + 32] = make_uint2(l0, l1);
}

// ================= bf16x3 GEMM, CTA 128x256, 512 threads, 64-k stages =======
// (EXACT R8 configuration — measured local optimum)
#define SUB_A 16384
#define SUB_B 32768
#define SUB_BYTES (SUB_A + SUB_B)        // 49152
#define STAGE_BYTES (2*SUB_BYTES)        // 98304
#define GEMM_SMEM (2*STAGE_BYTES + 256)  // NSTAGE=2
#define GTHREADS 512

__device__ __forceinline__ void gemm_k64(const __nv_bfloat16* __restrict__ Ap,
                                         const __nv_bfloat16* __restrict__ Bp,
                                         float* __restrict__ C,
                                         int N, int K, int bm, int bn, char* sm)
{
    const int tid  = threadIdx.x;          // 0..511
    const int lane = tid & 31;
    const int wid  = tid >> 5;             // 0..15
    const int wm = wid & 3;                // 4 m groups of 32 rows
    const int wn = wid >> 2;               // 4 n groups of 64 cols
    const uint32_t smb = (smem_u32(sm) + 127u) & ~127u;
    const int KT  = K >> 5;
    const int KT2 = K >> 6;

    const int r0  = tid >> 3;              // 0..63
    const int g16 = (tid & 7) * 16;
    uint32_t soffA[2], soffB[4];
#pragma unroll
    for (int q = 0; q < 2; ++q) soffA[q] = SWZ128((uint32_t)((r0 + q*64)*128 + g16));
#pragma unroll
    for (int q = 0; q < 4; ++q) soffB[q] = SWZ128((uint32_t)((r0 + q*64)*128 + g16));
    const char* Apb = (const char*)Ap + ((size_t)bm * 128) * (size_t)KT * 128;
    const char* Bpb = (const char*)Bp + ((size_t)bn * 256) * (size_t)KT * 128;

    const int lrow = ((lane >> 3) & 1) * 8 + (lane & 7);
    const int lkof = (lane >> 4) * 8;

    float acc[2][8][4];
#pragma unroll
    for (int i = 0; i < 2; ++i)
#pragma unroll
        for (int j = 0; j < 8; ++j)
#pragma unroll
            for (int r = 0; r < 4; ++r) acc[i][j][r] = 0.f;

    auto issue_stage = [&](int kt2, uint32_t sbase) {
#pragma unroll
        for (int sub = 0; sub < 2; ++sub) {
            const int kt = kt2*2 + sub;
            const uint32_t sa = sbase + sub * SUB_BYTES;
#pragma unroll
            for (int q = 0; q < 2; ++q)
                CP_ASYNC16(sa + soffA[q], Apb + ((size_t)(r0 + q*64) * KT + kt) * 128 + g16);
#pragma unroll
            for (int q = 0; q < 4; ++q)
                CP_ASYNC16(sa + SUB_A + soffB[q], Bpb + ((size_t)(r0 + q*64) * KT + kt) * 128 + g16);
        }
    };

    issue_stage(0, smb);
    CP_COMMIT();

    for (int kt2 = 0; kt2 < KT2; ++kt2) {
        CP_WAIT(0);
        __syncthreads();

        if (kt2 + 1 < KT2) issue_stage(kt2 + 1, smb + ((kt2 + 1) & 1) * STAGE_BYTES);
        CP_COMMIT();

        const uint32_t stg = smb + (kt2 & 1) * STAGE_BYTES;
#pragma unroll
        for (int sub = 0; sub < 2; ++sub) {
            const uint32_t sa = stg + sub * SUB_BYTES;
            const uint32_t sb = sa + SUB_A;
#pragma unroll
            for (int ks = 0; ks < 32; ks += 16) {
                uint32_t ah[2][4], al[2][4];
#pragma unroll
                for (int mt = 0; mt < 2; ++mt) {
                    uint32_t pre = (uint32_t)((wm*32 + mt*16 + lrow)*128 + (ks + lkof)*2);
                    uint32_t swz = SWZ128(pre);
                    LDMX4(ah[mt][0], ah[mt][1], ah[mt][2], ah[mt][3], sa + swz);
                    LDMX4(al[mt][0], al[mt][1], al[mt][2], al[mt][3], sa + (swz^64));
                }
                uint32_t bh[8][2], bl[8][2];
#pragma unroll
                for (int g = 0; g < 4; ++g) {
                    uint32_t pre = (uint32_t)((wn*64 + g*16 + lrow)*128 + (ks + lkof)*2);
                    uint32_t swz = SWZ128(pre);
                    uint32_t t0, t1, t2, t3;
                    LDMX4(t0, t1, t2, t3, sb + swz);
                    bh[2*g][0] = t0; bh[2*g][1] = t2;
                    bh[2*g+1][0] = t1; bh[2*g+1][1] = t3;
                    LDMX4(t0, t1, t2, t3, sb + (swz^64));
                    bl[2*g][0] = t0; bl[2*g][1] = t2;
                    bl[2*g+1][0] = t1; bl[2*g+1][1] = t3;
                }
                // term-major ordering: accumulator reuse separated by 15 MMAs
#pragma unroll
                for (int nt = 0; nt < 8; ++nt) {
                    MMA_BF16(acc[0][nt], ah[0], bh[nt]);
                    MMA_BF16(acc[1][nt], ah[1], bh[nt]);
                }
#pragma unroll
                for (int nt = 0; nt < 8; ++nt) {
                    MMA_BF16(acc[0][nt], ah[0], bl[nt]);
                    MMA_BF16(acc[1][nt], ah[1], bl[nt]);
                }
#pragma unroll
                for (int nt = 0; nt < 8; ++nt) {
                    MMA_BF16(acc[0][nt], al[0], bh[nt]);
                    MMA_BF16(acc[1][nt], al[1], bh[nt]);
                }
            }
        }
    }

    const int m0 = bm*128 + wm*32 + (lane >> 2);
    const int n0 = bn*256 + wn*64 + 2*(lane & 3);
#pragma unroll
    for (int mt = 0; mt < 2; ++mt)
#pragma unroll
        for (int nt = 0; nt < 8; ++nt) {
            float* c0 = C + (size_t)(m0 + mt*16) * N + n0 + nt*8;
            *(float2*)c0 = make_float2(acc[mt][nt][0], acc[mt][nt][1]);
            float* c1 = c0 + (size_t)8 * N;
            *(float2*)c1 = make_float2(acc[mt][nt][2], acc[mt][nt][3]);
        }
}

// merged qkv+z projection: bn 0..31 -> qkv, 32..47 -> z
__global__ void __launch_bounds__(GTHREADS, 1) gemm_qkvz(const __nv_bfloat16* __restrict__ xp,
                                                         const __nv_bfloat16* __restrict__ wqkvp,
                                                         const __nv_bfloat16* __restrict__ wzp,
                                                         float* __restrict__ qkv,
                                                         float* __restrict__ z)
{
    extern __shared__ char sm[];
    const int bn = blockIdx.x;
    if (bn < CONV_DIM/256)
        gemm_k64(xp, wqkvp, qkv, CONV_DIM, DIM, blockIdx.y, bn, sm);
    else
        gemm_k64(xp, wzp, z, VAL_DIM, DIM, blockIdx.y, bn - CONV_DIM/256, sm);
}

__global__ void __launch_bounds__(GTHREADS, 1) gemm_single(const __nv_bfloat16* __restrict__ Ap,
                                                           const __nv_bfloat16* __restrict__ Bp,
                                                           float* __restrict__ C,
                                                           int N, int K)
{
    extern __shared__ char sm[];
    gemm_k64(Ap, Bp, C, N, K, blockIdx.y, blockIdx.x, sm);
}

// ------------- small GEMM for a/b + fused g/beta epilogue -------------------
__global__ void __launch_bounds__(256) ab_gemm(const float* __restrict__ x,
                                               const float* __restrict__ Wa,
                                               const float* __restrict__ Wb,
                                               const float* __restrict__ A_log,
                                               const float* __restrict__ dt_bias,
                                               float* __restrict__ eg_out,
                                               float* __restrict__ beta_out)
{
    __shared__ float xs[16][65];
    __shared__ float ws[64][65];
    const int tid = threadIdx.x;
    const int m0  = blockIdx.x * 16;

    float acc[4] = {0.f, 0.f, 0.f, 0.f};
    const int r  = tid & 15;
    const int jg = tid >> 4;

    for (int k0 = 0; k0 < DIM; k0 += 64) {
        {
            int rr = tid >> 4;
            int cc = (tid & 15) * 4;
            float4 v = *(const float4*)&x[(size_t)(m0+rr)*DIM + k0 + cc];
            xs[rr][cc] = v.x; xs[rr][cc+1] = v.y; xs[rr][cc+2] = v.z; xs[rr][cc+3] = v.w;
        }
#pragma unroll
        for (int u = 0; u < 4; ++u) {
            int idx = tid + u*256;
            int j  = idx >> 4;
            int cc = (idx & 15) * 4;
            const float* W = (j < 32) ? &Wa[(size_t)j*DIM] : &Wb[(size_t)(j-32)*DIM];
            float4 v = *(const float4*)&W[k0 + cc];
            ws[j][cc] = v.x; ws[j][cc+1] = v.y; ws[j][cc+2] = v.z; ws[j][cc+3] = v.w;
        }
        __syncthreads();
#pragma unroll 8
        for (int k = 0; k < 64; ++k) {
            float xv = xs[r][k];
            acc[0] += xv * ws[jg*4+0][k];
            acc[1] += xv * ws[jg*4+1][k];
            acc[2] += xv * ws[jg*4+2][k];
            acc[3] += xv * ws[jg*4+3][k];
        }
        __syncthreads();
    }
    const int m = m0 + r;
#pragma unroll
    for (int u = 0; u < 4; ++u) {
        int j = jg*4 + u;
        float v = acc[u];
        if (j < 32) {
            float sp = v + dt_bias[j];
            sp = (sp > 20.f) ? sp : log1pf(expf(sp));
            eg_out[(size_t)m*HV + j] = expf(-expf(A_log[j]) * sp);
        } else {
            beta_out[(size_t)m*HV + (j-32)] = 1.f / (1.f + expf(-v));
        }
    }
}

// ------------- depthwise causal conv (K=4) + SiLU ---------------------------
__global__ void __launch_bounds__(256) conv_silu_kernel(const float* __restrict__ in,
                                                        float* __restrict__ out,
                                                        const float* __restrict__ w)
{
    const int c  = blockIdx.x * 256 + threadIdx.x;
    const int lc = blockIdx.y;
    const int b  = blockIdx.z;
    const float w0 = w[c*4+0], w1 = w[c*4+1], w2 = w[c*4+2], w3 = w[c*4+3];
    const float* ip = in  + (size_t)b*LL*CONV_DIM + c;
    float*       op = out + (size_t)b*LL*CONV_DIM + c;
    const int l0 = lc * 128;
    float xm3, xm2, xm1;
    if (l0 == 0) { xm3 = xm2 = xm1 = 0.f; }
    else {
        xm3 = ip[(size_t)(l0-3)*CONV_DIM];
        xm2 = ip[(size_t)(l0-2)*CONV_DIM];
        xm1 = ip[(size_t)(l0-1)*CONV_DIM];
    }
#pragma unroll 4
    for (int l = l0; l < l0 + 128; ++l) {
        float x0 = ip[(size_t)l*CONV_DIM];
        float h = xm3*w0 + xm2*w1 + xm1*w2 + x0*w3;
        h = h / (1.f + expf(-h));
        op[(size_t)l*CONV_DIM] = h;
        xm3 = xm2; xm2 = xm1; xm1 = x0;
    }
}

// ------------- l2norm of q and k heads (in place) ---------------------------
__global__ void __launch_bounds__(256) qknorm_kernel(float* __restrict__ d)
{
    const int wid  = (blockIdx.x * blockDim.x + threadIdx.x) >> 5;
    const int lane = threadIdx.x & 31;
    const int h2 = wid & 31;
    const int l  = (wid >> 5) & (LL-1);
    const int b  = wid >> 16;
    float* p = d + ((size_t)(b*LL + l))*CONV_DIM + h2*128 + lane*4;
    float4 v = *(float4*)p;
    float ss = v.x*v.x + v.y*v.y + v.z*v.z + v.w*v.w;
#pragma unroll
    for (int o = 16; o; o >>= 1) ss += __shfl_xor_sync(0xffffffffu, ss, o);
    float r = rsqrtf(ss + 1e-6f);
    if (h2 < 16) r *= 0.08838834764831845f;
    v.x *= r; v.y *= r; v.z *= r; v.w *= r;
    *(float4*)p = v;
}

// ------------- gated delta rule scan ----------------------------------------
// Triple-buffered cp.async loads (2-iter prefetch slack) + conflict-free smem
// layout (stride-33 per kq group: banks (kq+i)%32, no 4-way conflicts).
__global__ void __launch_bounds__(256, 1) scan_kernel(const float* __restrict__ qkv,
                                                      const float* __restrict__ eg,
                                                      const float* __restrict__ beta,
                                                      float* __restrict__ o)
{
    const int bi = blockIdx.x;
    const int vh = bi & 1;
    const int h  = (bi >> 1) & 31;
    const int b  = bi >> 6;
    const int hk = h >> 1;
    const int t  = threadIdx.x;
    const int kq   = t & 3;
    const int vloc = t >> 2;
    const int vcol = vh*64 + vloc;

    __shared__ float kq_s[3][272];      // per buf: k at kqg*33+i, q at 136+kqg*33+i
    __shared__ float v_s[3][64];
    __shared__ float egs[LL];
    __shared__ float bets[LL];

    for (int i = t; i < LL; i += 256) {
        egs[i]  = eg  [(size_t)(b*LL + i)*HV + h];
        bets[i] = beta[(size_t)(b*LL + i)*HV + h];
    }

    float s[32];
#pragma unroll
    for (int i = 0; i < 32; ++i) s[i] = 0.f;

    const float* base = qkv + (size_t)b*LL*CONV_DIM;
    const int kqoff = (t < 128) ? (KEY_DIM + hk*128 + t)
                                : (hk*128 + (t-128));
    const int e    = (t < 128) ? t : (t - 128);
    const int soff = ((t < 128) ? 0 : 136) + (e >> 5)*33 + (e & 31);
    const int voff = 2*KEY_DIM + h*128 + vcol;
    float* optr = o + (size_t)b*LL*VAL_DIM + h*128 + vcol;

    const uint32_t s_kq = smem_u32(&kq_s[0][0]);
    const uint32_t s_v  = smem_u32(&v_s[0][0]);

    // prologue: issue l=0, l=1
    {
        CP_ASYNC4(s_kq + (uint32_t)(0*272 + soff)*4, base + kqoff);
        if (kq == 0) CP_ASYNC4(s_v + (uint32_t)(0*64 + vloc)*4, base + voff);
        CP_COMMIT();
        CP_ASYNC4(s_kq + (uint32_t)(1*272 + soff)*4, base + (size_t)CONV_DIM + kqoff);
        if (kq == 0) CP_ASYNC4(s_v + (uint32_t)(1*64 + vloc)*4, base + (size_t)CONV_DIM + voff);
        CP_COMMIT();
        CP_WAIT(1);
    }
    __syncthreads();

    int buf = 0;
    for (int l = 0; l < LL; ++l) {
        // issue loads for l+2 into buffer (l+2)%3 (freed at end of iter l-1)
        if (l + 2 < LL) {
            const int nb = (buf + 2 >= 3) ? (buf - 1) : (buf + 2);
            CP_ASYNC4(s_kq + (uint32_t)(nb*272 + soff)*4,
                      base + (size_t)(l+2)*CONV_DIM + kqoff);
            if (kq == 0)
                CP_ASYNC4(s_v + (uint32_t)(nb*64 + vloc)*4,
                          base + (size_t)(l+2)*CONV_DIM + voff);
        }
        CP_COMMIT();

        const float egv  = egs[l];
        const float bv   = bets[l];
        const float vcur = v_s[buf][vloc];
        const float* ks = &kq_s[buf][kq*33];
        const float* qs = &kq_s[buf][136 + kq*33];

        float kv0 = 0.f, kv1 = 0.f, kv2 = 0.f, kv3 = 0.f;
#pragma unroll
        for (int i = 0; i < 8; ++i) {
            kv0 += ks[i]    * s[i];
            kv1 += ks[i+8]  * s[i+8];
            kv2 += ks[i+16] * s[i+16];
            kv3 += ks[i+24] * s[i+24];
        }
        float kv = (kv0 + kv1) + (kv2 + kv3);
        kv += __shfl_xor_sync(0xffffffffu, kv, 1);
        kv += __shfl_xor_sync(0xffffffffu, kv, 2);
        kv *= egv;
        const float delta = (vcur - kv) * bv;

        float o0 = 0.f, o1 = 0.f, o2 = 0.f, o3 = 0.f;
#pragma unroll
        for (int i = 0; i < 8; ++i) {
            s[i]    = egv*s[i]    + ks[i]*delta;    o0 += qs[i]*s[i];
            s[i+8]  = egv*s[i+8]  + ks[i+8]*delta;  o1 += qs[i+8]*s[i+8];
            s[i+16] = egv*s[i+16] + ks[i+16]*delta; o2 += qs[i+16]*s[i+16];
            s[i+24] = egv*s[i+24] + ks[i+24]*delta; o3 += qs[i+24]*s[i+24];
        }
        float outv = (o0 + o1) + (o2 + o3);
        outv += __shfl_xor_sync(0xffffffffu, outv, 1);
        outv += __shfl_xor_sync(0xffffffffu, outv, 2);
        if (kq == 0) optr[(size_t)l*VAL_DIM] = outv;

        // wait until at most 1 group outstanding: buffer for l+1 is ready
        CP_WAIT(1);
        __syncthreads();
        buf = (buf + 1 >= 3) ? 0 : (buf + 1);
    }
}

// ------------- gated RMSNorm + pack to bf16 hi/lo ---------------------------
__global__ void __launch_bounds__(256) rmsgate_pack_kernel(const float* __restrict__ o,
                                                           const float* __restrict__ z,
                                                           const float* __restrict__ nw,
                                                           __nv_bfloat16* __restrict__ op)
{
    const int wid  = (blockIdx.x * blockDim.x + threadIdx.x) >> 5;
    const int lane = threadIdx.x & 31;
    const float* p  = o + (size_t)wid*128 + lane*4;
    const float* zp = z + (size_t)wid*128 + lane*4;
    float4 v = *(const float4*)p;
    float ss = v.x*v.x + v.y*v.y + v.z*v.z + v.w*v.w;
#pragma unroll
    for (int off = 16; off; off >>= 1) ss += __shfl_xor_sync(0xffffffffu, ss, off);
    const float r = rsqrtf(ss * (1.f/128.f) + 1e-6f);
    float4 zv = *(const float4*)zp;
    float4 w4 = *(const float4*)&nw[lane*4];
    float4 out;
    out.x = v.x * r * w4.x * (zv.x / (1.f + expf(-zv.x)));
    out.y = v.y * r * w4.y * (zv.y / (1.f + expf(-zv.y)));
    out.z = v.z * r * w4.z * (zv.z / (1.f + expf(-zv.z)));
    out.w = v.w * r * w4.w * (zv.w / (1.f + expf(-zv.w)));
    const int m = wid >> 5;
    const int h = wid & 31;
    const int c = h*128 + lane*4;
    const int kt = c >> 5, j = c & 31;
    uint32_t h0, l0, h1, l1;
    split_pair(out.x, out.y, h0, l0);
    split_pair(out.z, out.w, h1, l1);
    size_t base = ((size_t)m * (VAL_DIM >> 5) + kt) * 64 + j;
    *(uint2*)&op[base]      = make_uint2(h0, h1);
    *(uint2*)&op[base + 32] = make_uint2(l0, l1);
}

// ---------------- launch ----------------------------------------------------
extern "C" void kernel_launch(void* const* d_in, const int* in_sizes, int n_in,
                              void* d_out, int out_size)
{
    const float* x       = (const float*)d_in[0];
    const float* W_qkv   = (const float*)d_in[1];
    const float* W_z     = (const float*)d_in[2];
    const float* W_a     = (const float*)d_in[3];
    const float* W_b     = (const float*)d_in[4];
    const float* conv_w  = (const float*)d_in[5];
    const float* A_log   = (const float*)d_in[6];
    const float* dt_bias = (const float*)d_in[7];
    const float* norm_w  = (const float*)d_in[8];
    const float* W_out   = (const float*)d_in[9];
    float* out = (float*)d_out;

    float *qkv, *cnv, *z, *eg, *bet, *o;
    __nv_bfloat16 *xp, *wqkvp, *wzp, *woutp, *op;
    cudaGetSymbolAddress((void**)&qkv, g_qkv);
    cudaGetSymbolAddress((void**)&cnv, g_conv);
    cudaGetSymbolAddress((void**)&z,   g_z);
    cudaGetSymbolAddress((void**)&eg,  g_eg);
    cudaGetSymbolAddress((void**)&bet, g_beta);
    cudaGetSymbolAddress((void**)&o,   g_o);
    cudaGetSymbolAddress((void**)&xp,    g_xp);
    cudaGetSymbolAddress((void**)&wqkvp, g_wqkvp);
    cudaGetSymbolAddress((void**)&wzp,   g_wzp);
    cudaGetSymbolAddress((void**)&woutp, g_woutp);
    cudaGetSymbolAddress((void**)&op,    g_op);

    cudaFuncSetAttribute(gemm_qkvz,   cudaFuncAttributeMaxDynamicSharedMemorySize, GEMM_SMEM);
    cudaFuncSetAttribute(gemm_single, cudaFuncAttributeMaxDynamicSharedMemorySize, GEMM_SMEM);

    // 0) packs — merged GEMM is the 4th launch (ncu capture)
    pack_kernel<<<(MTOT*DIM/4)/256, 256>>>(x, xp, DIM);
    pack_kernel<<<((size_t)CONV_DIM*DIM/4)/256, 256>>>(W_qkv, wqkvp, DIM);
    pack_kernel<<<((size_t)VAL_DIM*DIM/4)/256, 256>>>(W_z, wzp, DIM);
    // 1) merged qkv + z projection
    gemm_qkvz<<<dim3(CONV_DIM/256 + VAL_DIM/256, MTOT/128), GTHREADS, GEMM_SMEM>>>(
        xp, wqkvp, wzp, qkv, z);
    // 2) remaining pack + a/b
    pack_kernel<<<((size_t)DIM*VAL_DIM/4)/256, 256>>>(W_out, woutp, VAL_DIM);
    ab_gemm<<<MTOT/16, 256>>>(x, W_a, W_b, A_log, dt_bias, eg, bet);
    // 3) conv + qknorm
    conv_silu_kernel<<<dim3(CONV_DIM/256, LL/128, BB), 256>>>(qkv, cnv, conv_w);
    qknorm_kernel<<<(BB*LL*32)/8, 256>>>(cnv);
    // 4) scan (cp.async triple-buffered, conflict-free smem)
    scan_kernel<<<BB*HV*2, 256>>>(cnv, eg, bet, o);
    // 5) gated RMSNorm + pack
    rmsgate_pack_kernel<<<(BB*LL*HV)/8, 256>>>(o, z, norm_w, op);
    // 6) output projection
    gemm_single<<<dim3(DIM/256, MTOT/128), GTHREADS, GEMM_SMEM>>>(op, woutp, out, DIM, VAL_DIM);
}